// round 1
// baseline (speedup 1.0000x reference)
#include <cuda_runtime.h>
#include <math_constants.h>

#define NH 12
#define HD 64
#define EMB 768
#define NB 2
#define SEQ 2048
#define MROWS (NB*SEQ)   // 4096

// scratch (device globals: no allocation allowed)
__device__ float g_q[(size_t)NB*NH*SEQ*HD];
__device__ float g_k[(size_t)NB*NH*SEQ*HD];
__device__ float g_v[(size_t)NB*NH*SEQ*HD];
__device__ float g_ctx[(size_t)MROWS*EMB];

// ---------------------------------------------------------------------------
// GEMM  C[M,N] = A[M,K] @ B[N,K]^T   (both row-major, K-major: "NT" gemm)
// MODE 0: A = x, B = w_qkv, scatter into g_q/g_k/g_v ([B,H,S,D] layout)
// MODE 1: A = g_ctx, B = w_out, C = out + bias
// Tiles: 128x128x16, 256 threads, 8x8 per thread.
// ---------------------------------------------------------------------------
template<int MODE>
__global__ void __launch_bounds__(256) gemm_nt(const float* __restrict__ A,
                                               const float* __restrict__ Bm,
                                               const float* __restrict__ bias,
                                               float* __restrict__ C,
                                               int M, int N, int K)
{
    const int BM = 128, BN = 128, BK = 16;
    __shared__ float As[BK][BM + 4];
    __shared__ float Bs[BK][BN + 4];

    const int tid = threadIdx.x;
    const int tx = tid & 15, ty = tid >> 4;
    const int m0 = blockIdx.y * BM, n0 = blockIdx.x * BN;

    if (MODE == 1) A = g_ctx;

    const int lrow = tid >> 1;          // 0..127
    const int lk   = (tid & 1) * 8;     // 0 or 8
    const float* Ap = A  + (size_t)(m0 + lrow) * K + lk;
    const float* Bp = Bm + (size_t)(n0 + lrow) * K + lk;

    float acc[8][8];
    #pragma unroll
    for (int i = 0; i < 8; i++)
        #pragma unroll
        for (int j = 0; j < 8; j++) acc[i][j] = 0.f;

    for (int k0 = 0; k0 < K; k0 += BK) {
        float4 a0 = *(const float4*)(Ap + k0);
        float4 a1 = *(const float4*)(Ap + k0 + 4);
        float4 b0 = *(const float4*)(Bp + k0);
        float4 b1 = *(const float4*)(Bp + k0 + 4);
        __syncthreads();
        As[lk+0][lrow] = a0.x; As[lk+1][lrow] = a0.y;
        As[lk+2][lrow] = a0.z; As[lk+3][lrow] = a0.w;
        As[lk+4][lrow] = a1.x; As[lk+5][lrow] = a1.y;
        As[lk+6][lrow] = a1.z; As[lk+7][lrow] = a1.w;
        Bs[lk+0][lrow] = b0.x; Bs[lk+1][lrow] = b0.y;
        Bs[lk+2][lrow] = b0.z; Bs[lk+3][lrow] = b0.w;
        Bs[lk+4][lrow] = b1.x; Bs[lk+5][lrow] = b1.y;
        Bs[lk+6][lrow] = b1.z; Bs[lk+7][lrow] = b1.w;
        __syncthreads();
        #pragma unroll
        for (int kk = 0; kk < BK; kk++) {
            float a[8], b[8];
            *(float4*)&a[0] = *(const float4*)&As[kk][ty*8];
            *(float4*)&a[4] = *(const float4*)&As[kk][ty*8 + 4];
            *(float4*)&b[0] = *(const float4*)&Bs[kk][tx*8];
            *(float4*)&b[4] = *(const float4*)&Bs[kk][tx*8 + 4];
            #pragma unroll
            for (int i = 0; i < 8; i++)
                #pragma unroll
                for (int j = 0; j < 8; j++)
                    acc[i][j] = fmaf(a[i], b[j], acc[i][j]);
        }
    }

    if (MODE == 0) {
        // scatter to q/k/v in [B,H,S,D]
        #pragma unroll
        for (int i = 0; i < 8; i++) {
            int m = m0 + ty*8 + i;
            int bb = m >> 11;            // /SEQ
            int ss = m & (SEQ - 1);
            #pragma unroll
            for (int j4 = 0; j4 < 2; j4++) {
                int n = n0 + tx*8 + j4*4;
                int which = n / EMB;
                int rem = n - which * EMB;
                int hh = rem >> 6;
                int dd = rem & 63;
                float* dst = (which == 0) ? g_q : ((which == 1) ? g_k : g_v);
                float4 v4 = make_float4(acc[i][j4*4+0], acc[i][j4*4+1],
                                        acc[i][j4*4+2], acc[i][j4*4+3]);
                *(float4*)&dst[(((size_t)bb*NH + hh)*SEQ + ss)*HD + dd] = v4;
            }
        }
    } else {
        #pragma unroll
        for (int i = 0; i < 8; i++) {
            int m = m0 + ty*8 + i;
            #pragma unroll
            for (int j4 = 0; j4 < 2; j4++) {
                int n = n0 + tx*8 + j4*4;
                float4 bv = *(const float4*)&bias[n];
                float4 v4 = make_float4(acc[i][j4*4+0] + bv.x,
                                        acc[i][j4*4+1] + bv.y,
                                        acc[i][j4*4+2] + bv.z,
                                        acc[i][j4*4+3] + bv.w);
                *(float4*)&C[(size_t)m * N + n] = v4;
            }
        }
    }
}

// ---------------------------------------------------------------------------
// Flash attention: BQ=128 queries x BKV=128 keys per tile, D=64, 256 threads.
// Online softmax; scale folded into Q load; mask applied (0 -> -inf).
// Output written to g_ctx in [B,S,E] layout (E = h*64+d).
// ---------------------------------------------------------------------------
__global__ void __launch_bounds__(256) flash_attn(const int* __restrict__ mask)
{
    const int BQ = 128, BKV = 128;
    extern __shared__ float sm[];
    float* Qs = sm;                        // [128][68]
    float* Ks = Qs + 128*68;               // [128][68]
    float* Vs = Ks + 128*68;               // [128][64]
    float* Ps = Vs + 128*64;               // [128][132]

    const int tid = threadIdx.x;
    const int tx = tid & 15, ty = tid >> 4;
    const int q0 = blockIdx.x * BQ;
    const int h = blockIdx.y, b = blockIdx.z;

    const size_t head_off = ((size_t)(b*NH + h)) * SEQ * HD;
    const float* Qg = g_q + head_off;
    const float* Kg = g_k + head_off;
    const float* Vg = g_v + head_off;

    // load Q tile, pre-scaled by 1/sqrt(D) = 0.125
    for (int it = tid; it < BQ*HD/4; it += 256) {
        int r = it >> 4, c = (it & 15) * 4;
        float4 v = *(const float4*)(Qg + (size_t)(q0 + r)*HD + c);
        float4 sv = make_float4(v.x*0.125f, v.y*0.125f, v.z*0.125f, v.w*0.125f);
        *(float4*)&Qs[r*68 + c] = sv;
    }

    float m_i[8], l_i[8], o[8][4];
    #pragma unroll
    for (int i = 0; i < 8; i++) {
        m_i[i] = -CUDART_INF_F; l_i[i] = 0.f;
        o[i][0] = o[i][1] = o[i][2] = o[i][3] = 0.f;
    }
    __syncthreads();

    for (int kt = 0; kt < SEQ; kt += BKV) {
        __syncthreads();  // previous tile's reads of Ks/Vs complete
        for (int it = tid; it < BKV*HD/4; it += 256) {
            int r = it >> 4, c = (it & 15) * 4;
            *(float4*)&Ks[r*68 + c] = *(const float4*)(Kg + (size_t)(kt + r)*HD + c);
            *(float4*)&Vs[r*64 + c] = *(const float4*)(Vg + (size_t)(kt + r)*HD + c);
        }
        __syncthreads();

        // S = Q K^T
        float s[8][8];
        #pragma unroll
        for (int i = 0; i < 8; i++)
            #pragma unroll
            for (int j = 0; j < 8; j++) s[i][j] = 0.f;

        #pragma unroll 8
        for (int kk = 0; kk < HD; kk++) {
            float a[8], bq[8];
            #pragma unroll
            for (int i = 0; i < 8; i++) a[i]  = Qs[(ty*8 + i)*68 + kk];
            #pragma unroll
            for (int j = 0; j < 8; j++) bq[j] = Ks[(tx*8 + j)*68 + kk];
            #pragma unroll
            for (int i = 0; i < 8; i++)
                #pragma unroll
                for (int j = 0; j < 8; j++)
                    s[i][j] = fmaf(a[i], bq[j], s[i][j]);
        }

        // mask (int 0 -> -inf)
        #pragma unroll
        for (int i = 0; i < 8; i++) {
            size_t mrow = (size_t)(q0 + ty*8 + i) * SEQ + kt + tx*8;
            int4 ma = *(const int4*)(mask + mrow);
            int4 mb = *(const int4*)(mask + mrow + 4);
            if (ma.x == 0) s[i][0] = -CUDART_INF_F;
            if (ma.y == 0) s[i][1] = -CUDART_INF_F;
            if (ma.z == 0) s[i][2] = -CUDART_INF_F;
            if (ma.w == 0) s[i][3] = -CUDART_INF_F;
            if (mb.x == 0) s[i][4] = -CUDART_INF_F;
            if (mb.y == 0) s[i][5] = -CUDART_INF_F;
            if (mb.z == 0) s[i][6] = -CUDART_INF_F;
            if (mb.w == 0) s[i][7] = -CUDART_INF_F;
        }

        // online softmax row update (rows owned by 16 tx-lanes)
        #pragma unroll
        for (int i = 0; i < 8; i++) {
            float tm = s[i][0];
            #pragma unroll
            for (int j = 1; j < 8; j++) tm = fmaxf(tm, s[i][j]);
            #pragma unroll
            for (int off = 8; off > 0; off >>= 1)
                tm = fmaxf(tm, __shfl_xor_sync(0xffffffffu, tm, off));
            float mn = fmaxf(m_i[i], tm);
            float corr = __expf(m_i[i] - mn);
            float ps = 0.f;
            #pragma unroll
            for (int j = 0; j < 8; j++) {
                float p = __expf(s[i][j] - mn);
                s[i][j] = p;
                ps += p;
            }
            #pragma unroll
            for (int off = 8; off > 0; off >>= 1)
                ps += __shfl_xor_sync(0xffffffffu, ps, off);
            l_i[i] = l_i[i]*corr + ps;
            m_i[i] = mn;
            o[i][0] *= corr; o[i][1] *= corr; o[i][2] *= corr; o[i][3] *= corr;
            *(float4*)&Ps[(ty*8 + i)*132 + tx*8]     = make_float4(s[i][0], s[i][1], s[i][2], s[i][3]);
            *(float4*)&Ps[(ty*8 + i)*132 + tx*8 + 4] = make_float4(s[i][4], s[i][5], s[i][6], s[i][7]);
        }
        __syncthreads();

        // O += P V
        #pragma unroll 4
        for (int kk = 0; kk < BKV; kk++) {
            float4 bv = *(const float4*)&Vs[kk*64 + tx*4];
            #pragma unroll
            for (int i = 0; i < 8; i++) {
                float a = Ps[(ty*8 + i)*132 + kk];
                o[i][0] = fmaf(a, bv.x, o[i][0]);
                o[i][1] = fmaf(a, bv.y, o[i][1]);
                o[i][2] = fmaf(a, bv.z, o[i][2]);
                o[i][3] = fmaf(a, bv.w, o[i][3]);
            }
        }
    }

    // normalize + write to ctx [B,S,E]
    #pragma unroll
    for (int i = 0; i < 8; i++) {
        float inv = 1.0f / l_i[i];
        float4 v = make_float4(o[i][0]*inv, o[i][1]*inv, o[i][2]*inv, o[i][3]*inv);
        *(float4*)&g_ctx[(size_t)(b*SEQ + q0 + ty*8 + i)*EMB + h*64 + tx*4] = v;
    }
}

// ---------------------------------------------------------------------------
extern "C" void kernel_launch(void* const* d_in, const int* in_sizes, int n_in,
                              void* d_out, int out_size)
{
    const float* x     = (const float*)d_in[0];
    const int*   mask  = (const int*)  d_in[1];
    const float* w_qkv = (const float*)d_in[2];
    const float* w_out = (const float*)d_in[3];
    const float* b_out = (const float*)d_in[4];
    float* out = (float*)d_out;

    // 1) QKV projection: [4096, 768] @ [2304, 768]^T -> scatter q/k/v
    {
        dim3 grid(3*EMB/128, MROWS/128);  // 18 x 32
        gemm_nt<0><<<grid, 256>>>(x, w_qkv, nullptr, nullptr, MROWS, 3*EMB, EMB);
    }

    // 2) Flash attention
    {
        const int smem_bytes = 128*(68 + 68 + 64 + 132) * 4;  // 169984
        cudaFuncSetAttribute(flash_attn,
                             cudaFuncAttributeMaxDynamicSharedMemorySize,
                             smem_bytes);
        dim3 grid(SEQ/128, NH, NB);       // 16 x 12 x 2
        flash_attn<<<grid, 256, smem_bytes>>>(mask);
    }

    // 3) Output projection + bias: [4096, 768] @ [768, 768]^T + b
    {
        dim3 grid(EMB/128, MROWS/128);    // 6 x 32
        gemm_nt<1><<<grid, 256>>>(nullptr, w_out, b_out, out, MROWS, EMB, EMB);
    }
}

// round 2
// speedup vs baseline: 2.6187x; 2.6187x over previous
#include <cuda_runtime.h>
#include <math_constants.h>

#define NH 12
#define HD 64
#define EMB 768
#define NB 2
#define SEQ 2048
#define MROWS (NB*SEQ)   // 4096

// scratch (device globals: no allocation allowed)
__device__ float g_q[(size_t)NB*NH*SEQ*HD];
__device__ float g_k[(size_t)NB*NH*SEQ*HD];
__device__ float g_v[(size_t)NB*NH*SEQ*HD];
__device__ float g_ctx[(size_t)MROWS*EMB];
__device__ unsigned g_maskbits[(size_t)SEQ*SEQ/32];

__device__ __forceinline__ unsigned f2t(float f){
    unsigned u; asm("cvt.rna.tf32.f32 %0, %1;" : "=r"(u) : "f"(f)); return u;
}
__device__ __forceinline__ void split1(float x, unsigned &hi, unsigned &lo){
    hi = f2t(x);
    lo = f2t(x - __uint_as_float(hi));
}
__device__ __forceinline__ void mma8(float c[4], const unsigned a[4], const unsigned b[2]){
    asm volatile("mma.sync.aligned.m16n8k8.row.col.f32.tf32.tf32.f32 "
        "{%0,%1,%2,%3},{%4,%5,%6,%7},{%8,%9},{%0,%1,%2,%3};"
        : "+f"(c[0]), "+f"(c[1]), "+f"(c[2]), "+f"(c[3])
        : "r"(a[0]), "r"(a[1]), "r"(a[2]), "r"(a[3]), "r"(b[0]), "r"(b[1]));
}

// ---------------------------------------------------------------------------
// pack the int mask into bits (done once, reused by all heads/batches)
// ---------------------------------------------------------------------------
__global__ void pack_mask(const int* __restrict__ mask){
    int gid = blockIdx.x*256 + threadIdx.x;
    unsigned bal = __ballot_sync(0xffffffffu, mask[gid] != 0);
    if ((gid & 31) == 0) g_maskbits[gid>>5] = bal;
}

// ---------------------------------------------------------------------------
// GEMM C[M,N] = A[M,K] @ B[N,K]^T via tf32 mma. SPLIT=1 -> 3-pass (fp32-ish
// accuracy), SPLIT=0 -> single pass. MODE 0: scatter q/k/v. MODE 1: bias+out.
// Tiles 128x128x16, 8 warps as 2(m) x 4(n), warp tile 64x32.
// ---------------------------------------------------------------------------
template<int SPLIT, int MODE>
__global__ void __launch_bounds__(256) gemm_mma(const float* __restrict__ A,
                                                const float* __restrict__ Bm,
                                                const float* __restrict__ bias,
                                                float* __restrict__ C, int K)
{
    const int LDT = 20;  // stride 20: gcd(20,32)=4 -> conflict-free frag LDS
    __shared__ unsigned Ah[128*LDT], Bh[128*LDT];
    __shared__ unsigned Al[SPLIT ? 128*LDT : 4], Bl[SPLIT ? 128*LDT : 4];

    const int tid = threadIdx.x, lane = tid & 31, warp = tid >> 5;
    const int wm = warp >> 2, wn = warp & 3;
    const int m0 = blockIdx.y * 128, n0 = blockIdx.x * 128;

    if (MODE == 1) A = g_ctx;

    const int lrow = tid >> 1, lk = (tid & 1) * 8;
    const float* Ap = A  + (size_t)(m0 + lrow) * K + lk;
    const float* Bp = Bm + (size_t)(n0 + lrow) * K + lk;

    float acc[4][4][4];
    #pragma unroll
    for (int i = 0; i < 4; i++)
        #pragma unroll
        for (int j = 0; j < 4; j++)
            #pragma unroll
            for (int e = 0; e < 4; e++) acc[i][j][e] = 0.f;

    for (int k0 = 0; k0 < K; k0 += 16) {
        float4 a0 = *(const float4*)(Ap + k0);
        float4 a1 = *(const float4*)(Ap + k0 + 4);
        float4 b0 = *(const float4*)(Bp + k0);
        float4 b1 = *(const float4*)(Bp + k0 + 4);
        __syncthreads();
        {
            uint4 h, l;
            split1(a0.x, h.x, l.x); split1(a0.y, h.y, l.y);
            split1(a0.z, h.z, l.z); split1(a0.w, h.w, l.w);
            *(uint4*)&Ah[lrow*LDT + lk] = h; if (SPLIT) *(uint4*)&Al[lrow*LDT + lk] = l;
            split1(a1.x, h.x, l.x); split1(a1.y, h.y, l.y);
            split1(a1.z, h.z, l.z); split1(a1.w, h.w, l.w);
            *(uint4*)&Ah[lrow*LDT + lk + 4] = h; if (SPLIT) *(uint4*)&Al[lrow*LDT + lk + 4] = l;
            split1(b0.x, h.x, l.x); split1(b0.y, h.y, l.y);
            split1(b0.z, h.z, l.z); split1(b0.w, h.w, l.w);
            *(uint4*)&Bh[lrow*LDT + lk] = h; if (SPLIT) *(uint4*)&Bl[lrow*LDT + lk] = l;
            split1(b1.x, h.x, l.x); split1(b1.y, h.y, l.y);
            split1(b1.z, h.z, l.z); split1(b1.w, h.w, l.w);
            *(uint4*)&Bh[lrow*LDT + lk + 4] = h; if (SPLIT) *(uint4*)&Bl[lrow*LDT + lk + 4] = l;
        }
        __syncthreads();

        #pragma unroll
        for (int ks = 0; ks < 2; ks++) {
            const int kk = ks*8 + (lane & 3);
            unsigned ah[4][4], al[4][4];
            #pragma unroll
            for (int mt = 0; mt < 4; mt++) {
                int base = (wm*64 + mt*16 + (lane>>2))*LDT + kk;
                ah[mt][0] = Ah[base];           ah[mt][1] = Ah[base + 8*LDT];
                ah[mt][2] = Ah[base + 4];       ah[mt][3] = Ah[base + 8*LDT + 4];
                if (SPLIT) {
                    al[mt][0] = Al[base];       al[mt][1] = Al[base + 8*LDT];
                    al[mt][2] = Al[base + 4];   al[mt][3] = Al[base + 8*LDT + 4];
                }
            }
            #pragma unroll
            for (int nt = 0; nt < 4; nt++) {
                int bbase = (wn*32 + nt*8 + (lane>>2))*LDT + kk;
                unsigned bh[2] = { Bh[bbase], Bh[bbase + 4] };
                unsigned bl[2];
                if (SPLIT) { bl[0] = Bl[bbase]; bl[1] = Bl[bbase + 4]; }
                #pragma unroll
                for (int mt = 0; mt < 4; mt++) {
                    mma8(acc[mt][nt], ah[mt], bh);
                    if (SPLIT) {
                        mma8(acc[mt][nt], al[mt], bh);
                        mma8(acc[mt][nt], ah[mt], bl);
                    }
                }
            }
        }
    }

    // epilogue
    #pragma unroll
    for (int mt = 0; mt < 4; mt++) {
        #pragma unroll
        for (int nt = 0; nt < 4; nt++) {
            int m = m0 + wm*64 + mt*16 + (lane>>2);
            int n = n0 + wn*32 + nt*8 + 2*(lane&3);
            if (MODE == 0) {
                #pragma unroll
                for (int half = 0; half < 2; half++) {
                    int mm = m + half*8;
                    int bb = mm >> 11, ss = mm & (SEQ-1);
                    int which = (n >= 2*EMB) ? 2 : ((n >= EMB) ? 1 : 0);
                    int rem = n - which*EMB;
                    int hh = rem >> 6, dd = rem & 63;
                    float* dst = (which == 0) ? g_q : ((which == 1) ? g_k : g_v);
                    float2 v = make_float2(acc[mt][nt][half*2], acc[mt][nt][half*2+1]);
                    *(float2*)&dst[(((size_t)bb*NH + hh)*SEQ + ss)*HD + dd] = v;
                }
            } else {
                float2 bv = *(const float2*)&bias[n];
                float2 v0 = make_float2(acc[mt][nt][0] + bv.x, acc[mt][nt][1] + bv.y);
                float2 v1 = make_float2(acc[mt][nt][2] + bv.x, acc[mt][nt][3] + bv.y);
                *(float2*)&C[(size_t)m * EMB + n] = v0;
                *(float2*)&C[(size_t)(m+8) * EMB + n] = v1;
            }
        }
    }
}

// ---------------------------------------------------------------------------
// Flash attention with tf32 mma. QK^T split (3 mma), PV single. BQ=BKV=128.
// 8 warps, each owns a 16-row Q strip. Online softmax in registers.
// ---------------------------------------------------------------------------
__global__ void __launch_bounds__(256) flash_mma()
{
    const int LQ = 68;   // stride for Q/K tiles: gcd(68,32)=4 -> conflict-free
    const int LV = 72;   // stride for V tile: 72 mod 32 = 8 -> conflict-free
    extern __shared__ unsigned smu[];
    unsigned* Qh = smu;
    unsigned* Ql = Qh + 128*LQ;
    unsigned* Kh = Ql + 128*LQ;
    unsigned* Kl = Kh + 128*LQ;
    unsigned* Vs = Kl + 128*LQ;    // [128][72]
    unsigned* MW = Vs + 128*LV;    // [128][4] mask bit words

    const int tid = threadIdx.x, lane = tid & 31, warp = tid >> 5;
    const int wq = warp * 16;
    const int q0 = blockIdx.x * 128;
    const int h = blockIdx.y, b = blockIdx.z;

    const size_t head_off = ((size_t)(b*NH + h)) * SEQ * HD;
    const float* Qg = g_q + head_off;
    const float* Kg = g_k + head_off;
    const float* Vg = g_v + head_off;
    const unsigned* mb = g_maskbits + (size_t)q0 * (SEQ/32);

    // load Q (scaled by 1/8, split to hi/lo tf32)
    for (int t = tid; t < 128*16; t += 256) {
        int r = t >> 4, dg = (t & 15) * 4;
        float4 v = *(const float4*)(Qg + (size_t)(q0 + r)*HD + dg);
        uint4 hh, ll;
        split1(v.x*0.125f, hh.x, ll.x); split1(v.y*0.125f, hh.y, ll.y);
        split1(v.z*0.125f, hh.z, ll.z); split1(v.w*0.125f, hh.w, ll.w);
        *(uint4*)&Qh[r*LQ + dg] = hh;
        *(uint4*)&Ql[r*LQ + dg] = ll;
    }

    float mrow[2] = {-CUDART_INF_F, -CUDART_INF_F};
    float lsum[2] = {0.f, 0.f};
    float o[8][4];
    #pragma unroll
    for (int i = 0; i < 8; i++) { o[i][0]=o[i][1]=o[i][2]=o[i][3]=0.f; }

    for (int kt = 0; kt < SEQ; kt += 128) {
        __syncthreads();
        for (int t = tid; t < 128*16; t += 256) {
            int r = t >> 4, dg = (t & 15) * 4;
            float4 kv = *(const float4*)(Kg + (size_t)(kt + r)*HD + dg);
            uint4 hh, ll;
            split1(kv.x, hh.x, ll.x); split1(kv.y, hh.y, ll.y);
            split1(kv.z, hh.z, ll.z); split1(kv.w, hh.w, ll.w);
            *(uint4*)&Kh[r*LQ + dg] = hh;
            *(uint4*)&Kl[r*LQ + dg] = ll;
            float4 vv = *(const float4*)(Vg + (size_t)(kt + r)*HD + dg);
            uint4 vt = make_uint4(f2t(vv.x), f2t(vv.y), f2t(vv.z), f2t(vv.w));
            *(uint4*)&Vs[r*LV + dg] = vt;
        }
        for (int t = tid; t < 512; t += 256)
            MW[t] = mb[(size_t)(t>>2)*(SEQ/32) + (kt>>5) + (t&3)];
        __syncthreads();

        // S = Q K^T (split tf32: hh + lh + hl)
        float s[16][4];
        #pragma unroll
        for (int nt = 0; nt < 16; nt++) { s[nt][0]=s[nt][1]=s[nt][2]=s[nt][3]=0.f; }

        #pragma unroll
        for (int ks = 0; ks < 8; ks++) {
            const int kk = ks*8 + (lane & 3);
            int abase = (wq + (lane>>2))*LQ + kk;
            unsigned ah[4] = { Qh[abase], Qh[abase + 8*LQ], Qh[abase + 4], Qh[abase + 8*LQ + 4] };
            unsigned al[4] = { Ql[abase], Ql[abase + 8*LQ], Ql[abase + 4], Ql[abase + 8*LQ + 4] };
            #pragma unroll
            for (int nt = 0; nt < 16; nt++) {
                int bbase = (nt*8 + (lane>>2))*LQ + kk;
                unsigned bh[2] = { Kh[bbase], Kh[bbase + 4] };
                unsigned bl[2] = { Kl[bbase], Kl[bbase + 4] };
                mma8(s[nt], ah, bh);
                mma8(s[nt], al, bh);
                mma8(s[nt], ah, bl);
            }
        }

        // mask (fast path when all bits set)
        const int rl0 = wq + (lane>>2);
        {
            unsigned w0[4] = { MW[rl0*4], MW[rl0*4+1], MW[rl0*4+2], MW[rl0*4+3] };
            unsigned w1[4] = { MW[(rl0+8)*4], MW[(rl0+8)*4+1], MW[(rl0+8)*4+2], MW[(rl0+8)*4+3] };
            if ((w0[0]&w0[1]&w0[2]&w0[3]&w1[0]&w1[1]&w1[2]&w1[3]) != 0xffffffffu) {
                #pragma unroll
                for (int nt = 0; nt < 16; nt++) {
                    #pragma unroll
                    for (int e = 0; e < 2; e++) {
                        int c = nt*8 + 2*(lane&3) + e;
                        if (!((w0[c>>5] >> (c&31)) & 1u)) s[nt][e]   = -CUDART_INF_F;
                        if (!((w1[c>>5] >> (c&31)) & 1u)) s[nt][2+e] = -CUDART_INF_F;
                    }
                }
            }
        }

        // online softmax (two rows per thread: rl0 and rl0+8)
        float mx0 = -CUDART_INF_F, mx1 = -CUDART_INF_F;
        #pragma unroll
        for (int nt = 0; nt < 16; nt++) {
            mx0 = fmaxf(mx0, fmaxf(s[nt][0], s[nt][1]));
            mx1 = fmaxf(mx1, fmaxf(s[nt][2], s[nt][3]));
        }
        mx0 = fmaxf(mx0, __shfl_xor_sync(0xffffffffu, mx0, 1));
        mx0 = fmaxf(mx0, __shfl_xor_sync(0xffffffffu, mx0, 2));
        mx1 = fmaxf(mx1, __shfl_xor_sync(0xffffffffu, mx1, 1));
        mx1 = fmaxf(mx1, __shfl_xor_sync(0xffffffffu, mx1, 2));
        float mn0 = fmaxf(mrow[0], mx0), mn1 = fmaxf(mrow[1], mx1);
        float corr0 = __expf(mrow[0] - mn0), corr1 = __expf(mrow[1] - mn1);
        mrow[0] = mn0; mrow[1] = mn1;
        float ps0 = 0.f, ps1 = 0.f;
        #pragma unroll
        for (int nt = 0; nt < 16; nt++) {
            s[nt][0] = __expf(s[nt][0] - mn0); ps0 += s[nt][0];
            s[nt][1] = __expf(s[nt][1] - mn0); ps0 += s[nt][1];
            s[nt][2] = __expf(s[nt][2] - mn1); ps1 += s[nt][2];
            s[nt][3] = __expf(s[nt][3] - mn1); ps1 += s[nt][3];
        }
        ps0 += __shfl_xor_sync(0xffffffffu, ps0, 1);
        ps0 += __shfl_xor_sync(0xffffffffu, ps0, 2);
        ps1 += __shfl_xor_sync(0xffffffffu, ps1, 1);
        ps1 += __shfl_xor_sync(0xffffffffu, ps1, 2);
        lsum[0] = lsum[0]*corr0 + ps0;
        lsum[1] = lsum[1]*corr1 + ps1;
        #pragma unroll
        for (int i = 0; i < 8; i++) {
            o[i][0] *= corr0; o[i][1] *= corr0;
            o[i][2] *= corr1; o[i][3] *= corr1;
        }

        // O += P V  (P accum-fragments -> A-fragments via quad shuffles)
        const int base = lane & ~3;
        const int s0l = base | ((lane&3)>>1);
        const int s2l = base | (((lane&3)>>1) + 2);
        const bool odd = lane & 1;
        #pragma unroll
        for (int st = 0; st < 16; st++) {
            float v00 = __shfl_sync(0xffffffffu, s[st][0], s0l);
            float v01 = __shfl_sync(0xffffffffu, s[st][1], s0l);
            float v10 = __shfl_sync(0xffffffffu, s[st][2], s0l);
            float v11 = __shfl_sync(0xffffffffu, s[st][3], s0l);
            float v20 = __shfl_sync(0xffffffffu, s[st][0], s2l);
            float v21 = __shfl_sync(0xffffffffu, s[st][1], s2l);
            float v30 = __shfl_sync(0xffffffffu, s[st][2], s2l);
            float v31 = __shfl_sync(0xffffffffu, s[st][3], s2l);
            unsigned a[4] = { f2t(odd ? v01 : v00), f2t(odd ? v11 : v10),
                              f2t(odd ? v21 : v20), f2t(odd ? v31 : v30) };
            #pragma unroll
            for (int nd = 0; nd < 8; nd++) {
                int bbase = (st*8 + (lane&3))*LV + nd*8 + (lane>>2);
                unsigned bv[2] = { Vs[bbase], Vs[bbase + 4*LV] };
                mma8(o[nd], a, bv);
            }
        }
    }

    // epilogue: normalize + write ctx [B,S,E]
    float inv0 = 1.0f / lsum[0], inv1 = 1.0f / lsum[1];
    int rg = q0 + wq + (lane>>2);
    #pragma unroll
    for (int nd = 0; nd < 8; nd++) {
        int col = h*64 + nd*8 + 2*(lane&3);
        float2 v0 = make_float2(o[nd][0]*inv0, o[nd][1]*inv0);
        float2 v1 = make_float2(o[nd][2]*inv1, o[nd][3]*inv1);
        *(float2*)&g_ctx[(size_t)(b*SEQ + rg)*EMB + col] = v0;
        *(float2*)&g_ctx[(size_t)(b*SEQ + rg + 8)*EMB + col] = v1;
    }
}

// ---------------------------------------------------------------------------
extern "C" void kernel_launch(void* const* d_in, const int* in_sizes, int n_in,
                              void* d_out, int out_size)
{
    const float* x     = (const float*)d_in[0];
    const int*   mask  = (const int*)  d_in[1];
    const float* w_qkv = (const float*)d_in[2];
    const float* w_out = (const float*)d_in[3];
    const float* b_out = (const float*)d_in[4];
    float* out = (float*)d_out;

    // 0) mask -> bitmask
    pack_mask<<<SEQ*SEQ/32/8, 256>>>(mask);

    // 1) QKV projection (split tf32): [4096,768] @ [2304,768]^T -> q/k/v
    {
        dim3 grid(3*EMB/128, MROWS/128);  // 18 x 32
        gemm_mma<1,0><<<grid, 256>>>(x, w_qkv, nullptr, nullptr, EMB);
    }

    // 2) flash attention (split tf32 logits, single tf32 PV)
    {
        const int smem_bytes = (4*128*68 + 128*72 + 512) * 4;  // 178176
        cudaFuncSetAttribute(flash_mma,
                             cudaFuncAttributeMaxDynamicSharedMemorySize,
                             smem_bytes);
        dim3 grid(SEQ/128, NH, NB);       // 16 x 12 x 2
        flash_mma<<<grid, 256, smem_bytes>>>();
    }

    // 3) output projection + bias (single tf32)
    {
        dim3 grid(EMB/128, MROWS/128);    // 6 x 32
        gemm_mma<0,1><<<grid, 256>>>(nullptr, w_out, b_out, out, EMB);
    }
}

// round 3
// speedup vs baseline: 3.8442x; 1.4680x over previous
#include <cuda_runtime.h>
#include <cuda_bf16.h>
#include <math_constants.h>

#define NH 12
#define HD 64
#define EMB 768
#define NB 2
#define SEQ 2048
#define MROWS (NB*SEQ)   // 4096

// ---------------- device-global scratch (no allocation allowed) -------------
__device__ unsigned g_xh[(size_t)MROWS*384],  g_xl[(size_t)MROWS*384];
__device__ unsigned g_wqh[(size_t)2304*384],  g_wql[(size_t)2304*384];
__device__ unsigned g_wot[(size_t)EMB*EMB];
__device__ unsigned g_qh[(size_t)NB*NH*SEQ*32], g_ql[(size_t)NB*NH*SEQ*32];
__device__ unsigned g_kh[(size_t)NB*NH*SEQ*32], g_kl[(size_t)NB*NH*SEQ*32];
__device__ unsigned g_vt[(size_t)NB*NH*SEQ*64];
__device__ unsigned g_ctxt[(size_t)MROWS*EMB];
__device__ unsigned g_maskbits[(size_t)SEQ*SEQ/32];

// ---------------- helpers ----------------------------------------------------
__device__ __forceinline__ unsigned f2t(float f){
    unsigned u; asm("cvt.rna.tf32.f32 %0, %1;" : "=r"(u) : "f"(f)); return u;
}
__device__ __forceinline__ void split2(float x0, float x1, unsigned &hi, unsigned &lo){
    __nv_bfloat162 h = __floats2bfloat162_rn(x0, x1);
    float r0 = x0 - __low2float(h);
    float r1 = x1 - __high2float(h);
    __nv_bfloat162 l = __floats2bfloat162_rn(r0, r1);
    hi = *reinterpret_cast<unsigned*>(&h);
    lo = *reinterpret_cast<unsigned*>(&l);
}
__device__ __forceinline__ void mma8(float c[4], const unsigned a[4], const unsigned b[2]){
    asm volatile("mma.sync.aligned.m16n8k8.row.col.f32.tf32.tf32.f32 "
        "{%0,%1,%2,%3},{%4,%5,%6,%7},{%8,%9},{%0,%1,%2,%3};"
        : "+f"(c[0]), "+f"(c[1]), "+f"(c[2]), "+f"(c[3])
        : "r"(a[0]), "r"(a[1]), "r"(a[2]), "r"(a[3]), "r"(b[0]), "r"(b[1]));
}
__device__ __forceinline__ void mmabf(float c[4], const unsigned a[4], const unsigned b[2]){
    asm volatile("mma.sync.aligned.m16n8k16.row.col.f32.bf16.bf16.f32 "
        "{%0,%1,%2,%3},{%4,%5,%6,%7},{%8,%9},{%0,%1,%2,%3};"
        : "+f"(c[0]), "+f"(c[1]), "+f"(c[2]), "+f"(c[3])
        : "r"(a[0]), "r"(a[1]), "r"(a[2]), "r"(a[3]), "r"(b[0]), "r"(b[1]));
}
__device__ __forceinline__ void cp16(void* s, const void* g){
    unsigned sa = (unsigned)__cvta_generic_to_shared(s);
    asm volatile("cp.async.cg.shared.global [%0], [%1], 16;" :: "r"(sa), "l"(g));
}
#define CP_COMMIT() asm volatile("cp.async.commit_group;")
#define CP_WAIT(n)  asm volatile("cp.async.wait_group %0;" :: "n"(n))

// ---------------- small prep kernels -----------------------------------------
__global__ void pack_mask(const int* __restrict__ mask){
    int gid = blockIdx.x*256 + threadIdx.x;
    unsigned bal = __ballot_sync(0xffffffffu, mask[gid] != 0);
    if ((gid & 31) == 0) g_maskbits[gid>>5] = bal;
}
__global__ void cvt_split(const float* __restrict__ src, unsigned* __restrict__ dh,
                          unsigned* __restrict__ dl, int n2){
    int i = blockIdx.x*256 + threadIdx.x;
    if (i < n2){
        float2 v = ((const float2*)src)[i];
        unsigned h, l; split2(v.x, v.y, h, l);
        dh[i] = h; dl[i] = l;
    }
}
__global__ void cvt_tf32(const float* __restrict__ src, unsigned* __restrict__ d, int n){
    int i = blockIdx.x*256 + threadIdx.x;
    if (i < n) d[i] = f2t(src[i]);
}

// ---------------------------------------------------------------------------
// QKV GEMM: [4096,768] @ [2304,768]^T, split-bf16 (3 mma), cp.async 2-stage.
// Tile 128x128xBK32. 8 warps 2(m)x4(n). Epilogue scatters q/k (split pairs)
// and v (tf32) with q pre-scaled by 0.125.
// ---------------------------------------------------------------------------
__global__ void __launch_bounds__(256) gemm_qkv()
{
    const int LDA = 20;              // uints per row (16 data + 4 pad)
    extern __shared__ unsigned sm[];
    unsigned* SAh = sm;              // [2][128*20]
    unsigned* SAl = sm + 2*2560;
    unsigned* SBh = sm + 4*2560;
    unsigned* SBl = sm + 6*2560;

    const int tid = threadIdx.x, lane = tid & 31, warp = tid >> 5;
    const int wm = warp >> 2, wn = warp & 3;
    const int m0 = blockIdx.y * 128, n0 = blockIdx.x * 128;

    float acc[4][4][4];
    #pragma unroll
    for (int i=0;i<4;i++) for (int j=0;j<4;j++) for (int e=0;e<4;e++) acc[i][j][e]=0.f;

    const int r = tid >> 2, ch = (tid & 3) * 4;   // 128 rows x 4 chunks per matrix
    auto issue = [&](int buf, int p0){
        unsigned* ah = SAh + buf*2560; unsigned* al = SAl + buf*2560;
        unsigned* bh = SBh + buf*2560; unsigned* bl = SBl + buf*2560;
        #pragma unroll
        for (int rep = 0; rep < 2; rep++){
            int rr = r + rep*64;
            cp16(&ah[rr*LDA + ch], g_xh  + (size_t)(m0+rr)*384 + p0 + ch);
            cp16(&al[rr*LDA + ch], g_xl  + (size_t)(m0+rr)*384 + p0 + ch);
            cp16(&bh[rr*LDA + ch], g_wqh + (size_t)(n0+rr)*384 + p0 + ch);
            cp16(&bl[rr*LDA + ch], g_wql + (size_t)(n0+rr)*384 + p0 + ch);
        }
    };

    const int T = 24;                 // 768/32 k-iters, 16 pairs each
    issue(0, 0); CP_COMMIT();
    for (int t = 0; t < T; t++){
        int buf = t & 1;
        if (t+1 < T){ issue(buf^1, (t+1)*16); CP_COMMIT(); CP_WAIT(1); }
        else CP_WAIT(0);
        __syncthreads();
        unsigned* ah_ = SAh + buf*2560; unsigned* al_ = SAl + buf*2560;
        unsigned* bh_ = SBh + buf*2560; unsigned* bl_ = SBl + buf*2560;
        #pragma unroll
        for (int ks = 0; ks < 2; ks++){
            const int q2 = ks*8 + (lane & 3);
            unsigned Ah[4][4], Al[4][4];
            #pragma unroll
            for (int mt=0; mt<4; mt++){
                int base = (wm*64 + mt*16 + (lane>>2))*LDA + q2;
                Ah[mt][0]=ah_[base];      Ah[mt][1]=ah_[base+8*LDA];
                Ah[mt][2]=ah_[base+4];    Ah[mt][3]=ah_[base+8*LDA+4];
                Al[mt][0]=al_[base];      Al[mt][1]=al_[base+8*LDA];
                Al[mt][2]=al_[base+4];    Al[mt][3]=al_[base+8*LDA+4];
            }
            #pragma unroll
            for (int nt=0; nt<4; nt++){
                int bbase = (wn*32 + nt*8 + (lane>>2))*LDA + q2;
                unsigned Bh[2] = { bh_[bbase], bh_[bbase+4] };
                unsigned Bl[2] = { bl_[bbase], bl_[bbase+4] };
                #pragma unroll
                for (int mt=0; mt<4; mt++){
                    mmabf(acc[mt][nt], Ah[mt], Bh);
                    mmabf(acc[mt][nt], Al[mt], Bh);
                    mmabf(acc[mt][nt], Ah[mt], Bl);
                }
            }
        }
        __syncthreads();
    }

    // epilogue: scatter q (scaled, split), k (split), v (tf32)
    #pragma unroll
    for (int mt=0; mt<4; mt++){
        #pragma unroll
        for (int nt=0; nt<4; nt++){
            int m = m0 + wm*64 + mt*16 + (lane>>2);
            int n = n0 + wn*32 + nt*8 + 2*(lane&3);
            int which = (n >= 2*EMB) ? 2 : ((n >= EMB) ? 1 : 0);
            int rem = n - which*EMB;
            int hh = rem >> 6, dd = rem & 63;
            #pragma unroll
            for (int half=0; half<2; half++){
                int mm = m + half*8;
                float v0 = acc[mt][nt][half*2], v1 = acc[mt][nt][half*2+1];
                size_t base = (((size_t)(mm>>11)*NH + hh)*SEQ + (mm & (SEQ-1)));
                if (which == 0){
                    unsigned h,l; split2(v0*0.125f, v1*0.125f, h, l);
                    g_qh[base*32 + (dd>>1)] = h; g_ql[base*32 + (dd>>1)] = l;
                } else if (which == 1){
                    unsigned h,l; split2(v0, v1, h, l);
                    g_kh[base*32 + (dd>>1)] = h; g_kl[base*32 + (dd>>1)] = l;
                } else {
                    g_vt[base*64 + dd]   = f2t(v0);
                    g_vt[base*64 + dd+1] = f2t(v1);
                }
            }
        }
    }
}

// ---------------------------------------------------------------------------
// Flash attention: BQ=BKV=128. QK^T split-bf16 (3 mma, k16), PV single tf32.
// K/V double-buffered via cp.async. Mask via packed bits (direct LDG).
// ---------------------------------------------------------------------------
__global__ void __launch_bounds__(256) flash_mma()
{
    const int LQ = 36;   // uints/row for Q,K pair tiles (32 + 4 pad)
    const int LV = 72;   // uints/row for V tf32 tile (64 + 8 pad)
    extern __shared__ unsigned smu[];
    unsigned* Qh = smu;                    // [128*36]
    unsigned* Ql = smu + 4608;
    unsigned* KH = smu + 9216;             // [2][128*36]
    unsigned* KL = smu + 18432;
    unsigned* VS = smu + 27648;            // [2][128*72]

    const int tid = threadIdx.x, lane = tid & 31, warp = tid >> 5;
    const int wq = warp * 16;
    const int q0 = blockIdx.x * 128;
    const int h = blockIdx.y, b = blockIdx.z;

    const size_t head = ((size_t)(b*NH + h)) * SEQ;
    const unsigned* qh = g_qh + head*32; const unsigned* ql = g_ql + head*32;
    const unsigned* kh = g_kh + head*32; const unsigned* kl = g_kl + head*32;
    const unsigned* vt = g_vt + head*64;

    // Q tile (goes into first cp.async group together with KV tile 0)
    for (int t = tid; t < 1024; t += 256){
        int r = t >> 3, c = (t & 7) * 4;
        cp16(&Qh[r*LQ + c], qh + (size_t)(q0 + r)*32 + c);
        cp16(&Ql[r*LQ + c], ql + (size_t)(q0 + r)*32 + c);
    }
    auto issue_kv = [&](int buf, int kt){
        unsigned* kh_ = KH + buf*4608; unsigned* kl_ = KL + buf*4608;
        unsigned* vs_ = VS + buf*9216;
        for (int t = tid; t < 1024; t += 256){
            int r = t >> 3, c = (t & 7) * 4;
            cp16(&kh_[r*LQ + c], kh + (size_t)(kt + r)*32 + c);
            cp16(&kl_[r*LQ + c], kl + (size_t)(kt + r)*32 + c);
        }
        for (int t = tid; t < 2048; t += 256){
            int r = t >> 4, c = (t & 15) * 4;
            cp16(&vs_[r*LV + c], vt + (size_t)(kt + r)*64 + c);
        }
    };

    float mrow[2] = {-CUDART_INF_F, -CUDART_INF_F};
    float lsum[2] = {0.f, 0.f};
    float o[8][4];
    #pragma unroll
    for (int i=0;i<8;i++){ o[i][0]=o[i][1]=o[i][2]=o[i][3]=0.f; }

    const int rl0 = wq + (lane>>2);
    const unsigned* mrow0 = g_maskbits + (size_t)(q0 + rl0)     * (SEQ/32);
    const unsigned* mrow1 = g_maskbits + (size_t)(q0 + rl0 + 8) * (SEQ/32);

    issue_kv(0, 0); CP_COMMIT();
    const int T = SEQ/128;
    for (int t = 0; t < T; t++){
        int buf = t & 1;
        if (t+1 < T){ issue_kv(buf^1, (t+1)*128); CP_COMMIT(); CP_WAIT(1); }
        else CP_WAIT(0);
        __syncthreads();
        unsigned* kh_ = KH + buf*4608; unsigned* kl_ = KL + buf*4608;
        unsigned* vs_ = VS + buf*9216;
        const int kt = t*128;

        // S = Q K^T (split bf16: hh + lh + hl)
        float s[16][4];
        #pragma unroll
        for (int nt=0; nt<16; nt++){ s[nt][0]=s[nt][1]=s[nt][2]=s[nt][3]=0.f; }

        #pragma unroll
        for (int ks = 0; ks < 4; ks++){
            const int q2 = ks*8 + (lane & 3);
            int abase = (wq + (lane>>2))*LQ + q2;
            unsigned Ah[4] = { Qh[abase], Qh[abase+8*LQ], Qh[abase+4], Qh[abase+8*LQ+4] };
            unsigned Al[4] = { Ql[abase], Ql[abase+8*LQ], Ql[abase+4], Ql[abase+8*LQ+4] };
            #pragma unroll
            for (int nt=0; nt<16; nt++){
                int bbase = (nt*8 + (lane>>2))*LQ + q2;
                unsigned Bh[2] = { kh_[bbase], kh_[bbase+4] };
                unsigned Bl[2] = { kl_[bbase], kl_[bbase+4] };
                mmabf(s[nt], Ah, Bh);
                mmabf(s[nt], Al, Bh);
                mmabf(s[nt], Ah, Bl);
            }
        }

        // mask
        {
            int w = kt >> 5;
            unsigned w0[4] = { mrow0[w], mrow0[w+1], mrow0[w+2], mrow0[w+3] };
            unsigned w1[4] = { mrow1[w], mrow1[w+1], mrow1[w+2], mrow1[w+3] };
            if ((w0[0]&w0[1]&w0[2]&w0[3]&w1[0]&w1[1]&w1[2]&w1[3]) != 0xffffffffu){
                #pragma unroll
                for (int nt=0; nt<16; nt++){
                    #pragma unroll
                    for (int e=0; e<2; e++){
                        int c = nt*8 + 2*(lane&3) + e;
                        if (!((w0[c>>5] >> (c&31)) & 1u)) s[nt][e]   = -CUDART_INF_F;
                        if (!((w1[c>>5] >> (c&31)) & 1u)) s[nt][2+e] = -CUDART_INF_F;
                    }
                }
            }
        }

        // online softmax (rows rl0, rl0+8)
        float mx0 = -CUDART_INF_F, mx1 = -CUDART_INF_F;
        #pragma unroll
        for (int nt=0; nt<16; nt++){
            mx0 = fmaxf(mx0, fmaxf(s[nt][0], s[nt][1]));
            mx1 = fmaxf(mx1, fmaxf(s[nt][2], s[nt][3]));
        }
        mx0 = fmaxf(mx0, __shfl_xor_sync(0xffffffffu, mx0, 1));
        mx0 = fmaxf(mx0, __shfl_xor_sync(0xffffffffu, mx0, 2));
        mx1 = fmaxf(mx1, __shfl_xor_sync(0xffffffffu, mx1, 1));
        mx1 = fmaxf(mx1, __shfl_xor_sync(0xffffffffu, mx1, 2));
        float mn0 = fmaxf(mrow[0], mx0), mn1 = fmaxf(mrow[1], mx1);
        float corr0 = __expf(mrow[0]-mn0), corr1 = __expf(mrow[1]-mn1);
        mrow[0] = mn0; mrow[1] = mn1;
        float ps0 = 0.f, ps1 = 0.f;
        #pragma unroll
        for (int nt=0; nt<16; nt++){
            s[nt][0] = __expf(s[nt][0]-mn0); ps0 += s[nt][0];
            s[nt][1] = __expf(s[nt][1]-mn0); ps0 += s[nt][1];
            s[nt][2] = __expf(s[nt][2]-mn1); ps1 += s[nt][2];
            s[nt][3] = __expf(s[nt][3]-mn1); ps1 += s[nt][3];
        }
        ps0 += __shfl_xor_sync(0xffffffffu, ps0, 1);
        ps0 += __shfl_xor_sync(0xffffffffu, ps0, 2);
        ps1 += __shfl_xor_sync(0xffffffffu, ps1, 1);
        ps1 += __shfl_xor_sync(0xffffffffu, ps1, 2);
        lsum[0] = lsum[0]*corr0 + ps0;
        lsum[1] = lsum[1]*corr1 + ps1;
        #pragma unroll
        for (int i=0;i<8;i++){
            o[i][0]*=corr0; o[i][1]*=corr0; o[i][2]*=corr1; o[i][3]*=corr1;
        }

        // O += P V  (accum fragments -> A fragments via quad shuffles, tf32)
        const int base2 = lane & ~3;
        const int s0l = base2 | ((lane&3)>>1);
        const int s2l = base2 | (((lane&3)>>1) + 2);
        const bool odd = lane & 1;
        #pragma unroll
        for (int st=0; st<16; st++){
            float v00 = __shfl_sync(0xffffffffu, s[st][0], s0l);
            float v01 = __shfl_sync(0xffffffffu, s[st][1], s0l);
            float v10 = __shfl_sync(0xffffffffu, s[st][2], s0l);
            float v11 = __shfl_sync(0xffffffffu, s[st][3], s0l);
            float v20 = __shfl_sync(0xffffffffu, s[st][0], s2l);
            float v21 = __shfl_sync(0xffffffffu, s[st][1], s2l);
            float v30 = __shfl_sync(0xffffffffu, s[st][2], s2l);
            float v31 = __shfl_sync(0xffffffffu, s[st][3], s2l);
            unsigned a[4] = { f2t(odd ? v01 : v00), f2t(odd ? v11 : v10),
                              f2t(odd ? v21 : v20), f2t(odd ? v31 : v30) };
            #pragma unroll
            for (int nd=0; nd<8; nd++){
                int bbase = (st*8 + (lane&3))*LV + nd*8 + (lane>>2);
                unsigned bv[2] = { vs_[bbase], vs_[bbase + 4*LV] };
                mma8(o[nd], a, bv);
            }
        }
        __syncthreads();
    }

    // epilogue: normalize + write ctx as tf32 pairs
    float inv0 = 1.0f/lsum[0], inv1 = 1.0f/lsum[1];
    int rg = q0 + wq + (lane>>2);
    #pragma unroll
    for (int nd=0; nd<8; nd++){
        int col = h*64 + nd*8 + 2*(lane&3);
        uint2 u0 = make_uint2(f2t(o[nd][0]*inv0), f2t(o[nd][1]*inv0));
        uint2 u1 = make_uint2(f2t(o[nd][2]*inv1), f2t(o[nd][3]*inv1));
        *(uint2*)&g_ctxt[(size_t)(b*SEQ + rg)*EMB + col] = u0;
        *(uint2*)&g_ctxt[(size_t)(b*SEQ + rg + 8)*EMB + col] = u1;
    }
}

// ---------------------------------------------------------------------------
// Out projection: [4096,768] @ [768,768]^T + bias, single tf32, cp.async.
// ---------------------------------------------------------------------------
__global__ void __launch_bounds__(256) gemm_out(const float* __restrict__ bias,
                                                float* __restrict__ C)
{
    const int LDA = 20;
    extern __shared__ unsigned sm[];
    unsigned* SA = sm;              // [2][128*20]
    unsigned* SB = sm + 2*2560;

    const int tid = threadIdx.x, lane = tid & 31, warp = tid >> 5;
    const int wm = warp >> 2, wn = warp & 3;
    const int m0 = blockIdx.y * 128, n0 = blockIdx.x * 128;

    float acc[4][4][4];
    #pragma unroll
    for (int i=0;i<4;i++) for (int j=0;j<4;j++) for (int e=0;e<4;e++) acc[i][j][e]=0.f;

    const int r = tid >> 1, ch = (tid & 1) * 8;   // 128 rows x 2 chunk-pairs
    auto issue = [&](int buf, int p0){
        unsigned* a_ = SA + buf*2560; unsigned* b_ = SB + buf*2560;
        cp16(&a_[r*LDA + ch],     g_ctxt + (size_t)(m0+r)*EMB + p0 + ch);
        cp16(&a_[r*LDA + ch + 4], g_ctxt + (size_t)(m0+r)*EMB + p0 + ch + 4);
        cp16(&b_[r*LDA + ch],     g_wot  + (size_t)(n0+r)*EMB + p0 + ch);
        cp16(&b_[r*LDA + ch + 4], g_wot  + (size_t)(n0+r)*EMB + p0 + ch + 4);
    };

    const int T = EMB/16;   // 48
    issue(0, 0); CP_COMMIT();
    for (int t = 0; t < T; t++){
        int buf = t & 1;
        if (t+1 < T){ issue(buf^1, (t+1)*16); CP_COMMIT(); CP_WAIT(1); }
        else CP_WAIT(0);
        __syncthreads();
        unsigned* a_ = SA + buf*2560; unsigned* b_ = SB + buf*2560;
        #pragma unroll
        for (int ks = 0; ks < 2; ks++){
            const int kk = ks*8 + (lane & 3);
            unsigned A[4][4];
            #pragma unroll
            for (int mt=0; mt<4; mt++){
                int base = (wm*64 + mt*16 + (lane>>2))*LDA + kk;
                A[mt][0]=a_[base];   A[mt][1]=a_[base+8*LDA];
                A[mt][2]=a_[base+4]; A[mt][3]=a_[base+8*LDA+4];
            }
            #pragma unroll
            for (int nt=0; nt<4; nt++){
                int bbase = (wn*32 + nt*8 + (lane>>2))*LDA + kk;
                unsigned B[2] = { b_[bbase], b_[bbase+4] };
                #pragma unroll
                for (int mt=0; mt<4; mt++) mma8(acc[mt][nt], A[mt], B);
            }
        }
        __syncthreads();
    }

    #pragma unroll
    for (int mt=0; mt<4; mt++){
        #pragma unroll
        for (int nt=0; nt<4; nt++){
            int m = m0 + wm*64 + mt*16 + (lane>>2);
            int n = n0 + wn*32 + nt*8 + 2*(lane&3);
            float2 bv = *(const float2*)&bias[n];
            float2 v0 = make_float2(acc[mt][nt][0]+bv.x, acc[mt][nt][1]+bv.y);
            float2 v1 = make_float2(acc[mt][nt][2]+bv.x, acc[mt][nt][3]+bv.y);
            *(float2*)&C[(size_t)m*EMB + n] = v0;
            *(float2*)&C[(size_t)(m+8)*EMB + n] = v1;
        }
    }
}

// ---------------------------------------------------------------------------
extern "C" void kernel_launch(void* const* d_in, const int* in_sizes, int n_in,
                              void* d_out, int out_size)
{
    const float* x     = (const float*)d_in[0];
    const int*   mask  = (const int*)  d_in[1];
    const float* w_qkv = (const float*)d_in[2];
    const float* w_out = (const float*)d_in[3];
    const float* b_out = (const float*)d_in[4];
    float* out = (float*)d_out;

    static unsigned *p_xh=nullptr,*p_xl,*p_wqh,*p_wql,*p_wot;
    // resolve device-global addresses once per process (host-side, not capture-unsafe state)
    if (!p_xh){
        cudaGetSymbolAddress((void**)&p_xh,  g_xh);
        cudaGetSymbolAddress((void**)&p_xl,  g_xl);
        cudaGetSymbolAddress((void**)&p_wqh, g_wqh);
        cudaGetSymbolAddress((void**)&p_wql, g_wql);
        cudaGetSymbolAddress((void**)&p_wot, g_wot);
    }

    pack_mask<<<SEQ*SEQ/32/8, 256>>>(mask);
    cvt_split<<<(MROWS*384)/256, 256>>>(x,     p_xh,  p_xl,  MROWS*384);
    cvt_split<<<(2304*384)/256, 256>>>(w_qkv, p_wqh, p_wql, 2304*384);
    cvt_tf32 <<<(EMB*EMB)/256,  256>>>(w_out, p_wot, EMB*EMB);

    {   // QKV projection
        cudaFuncSetAttribute(gemm_qkv, cudaFuncAttributeMaxDynamicSharedMemorySize, 81920);
        dim3 grid(2304/128, MROWS/128);   // 18 x 32
        gemm_qkv<<<grid, 256, 81920>>>();
    }
    {   // flash attention
        const int smem_bytes = 46080*4;   // 184320
        cudaFuncSetAttribute(flash_mma, cudaFuncAttributeMaxDynamicSharedMemorySize, smem_bytes);
        dim3 grid(SEQ/128, NH, NB);       // 16 x 12 x 2
        flash_mma<<<grid, 256, smem_bytes>>>();
    }
    {   // out projection
        dim3 grid(EMB/128, MROWS/128);    // 6 x 32
        gemm_out<<<grid, 256, 40960>>>(b_out, out);
    }
}

// round 4
// speedup vs baseline: 4.6479x; 1.2091x over previous
#include <cuda_runtime.h>
#include <cuda_bf16.h>
#include <cuda_fp16.h>
#include <math_constants.h>

#define NH 12
#define HD 64
#define EMB 768
#define NB 2
#define SEQ 2048
#define MROWS (NB*SEQ)   // 4096

// ---------------- device-global scratch (no allocation allowed) -------------
__device__ unsigned g_xh[(size_t)MROWS*384],  g_xl[(size_t)MROWS*384];   // bf16 split pairs
__device__ unsigned g_wqh[(size_t)2304*384],  g_wql[(size_t)2304*384];
__device__ unsigned g_wot[(size_t)EMB*EMB/2];                            // fp16 pairs
__device__ unsigned g_qh[(size_t)NB*NH*SEQ*32], g_ql[(size_t)NB*NH*SEQ*32]; // fp16 split pairs
__device__ unsigned g_kh[(size_t)NB*NH*SEQ*32], g_kl[(size_t)NB*NH*SEQ*32];
__device__ unsigned g_vt[(size_t)NB*NH*HD*SEQ/2];                        // V^T fp16 [b,h][d][s]
__device__ unsigned g_ctxt[(size_t)MROWS*384];                           // ctx fp16 pairs
__device__ unsigned g_maskbits[(size_t)SEQ*SEQ/32];

// ---------------- helpers ----------------------------------------------------
__device__ __forceinline__ void split2(float x0, float x1, unsigned &hi, unsigned &lo){
    __nv_bfloat162 h = __floats2bfloat162_rn(x0, x1);
    float r0 = x0 - __low2float(h);
    float r1 = x1 - __high2float(h);
    __nv_bfloat162 l = __floats2bfloat162_rn(r0, r1);
    hi = *reinterpret_cast<unsigned*>(&h);
    lo = *reinterpret_cast<unsigned*>(&l);
}
__device__ __forceinline__ void split2h(float x0, float x1, unsigned &hi, unsigned &lo){
    __half2 h = __floats2half2_rn(x0, x1);
    float r0 = x0 - __low2float(h);
    float r1 = x1 - __high2float(h);
    __half2 l = __floats2half2_rn(r0, r1);
    hi = *reinterpret_cast<unsigned*>(&h);
    lo = *reinterpret_cast<unsigned*>(&l);
}
__device__ __forceinline__ unsigned packh(float x0, float x1){
    __half2 h = __floats2half2_rn(x0, x1);
    return *reinterpret_cast<unsigned*>(&h);
}
__device__ __forceinline__ void mmabf(float c[4], const unsigned a[4], const unsigned b[2]){
    asm volatile("mma.sync.aligned.m16n8k16.row.col.f32.bf16.bf16.f32 "
        "{%0,%1,%2,%3},{%4,%5,%6,%7},{%8,%9},{%0,%1,%2,%3};"
        : "+f"(c[0]), "+f"(c[1]), "+f"(c[2]), "+f"(c[3])
        : "r"(a[0]), "r"(a[1]), "r"(a[2]), "r"(a[3]), "r"(b[0]), "r"(b[1]));
}
__device__ __forceinline__ void mmah(float c[4], const unsigned a[4], const unsigned b[2]){
    asm volatile("mma.sync.aligned.m16n8k16.row.col.f32.f16.f16.f32 "
        "{%0,%1,%2,%3},{%4,%5,%6,%7},{%8,%9},{%0,%1,%2,%3};"
        : "+f"(c[0]), "+f"(c[1]), "+f"(c[2]), "+f"(c[3])
        : "r"(a[0]), "r"(a[1]), "r"(a[2]), "r"(a[3]), "r"(b[0]), "r"(b[1]));
}
__device__ __forceinline__ void cp16(void* s, const void* g){
    unsigned sa = (unsigned)__cvta_generic_to_shared(s);
    asm volatile("cp.async.cg.shared.global [%0], [%1], 16;" :: "r"(sa), "l"(g));
}
#define CP_COMMIT() asm volatile("cp.async.commit_group;")
#define CP_WAIT(n)  asm volatile("cp.async.wait_group %0;" :: "n"(n))

// ---------------- small prep kernels -----------------------------------------
__global__ void pack_mask(const int* __restrict__ mask){
    int gid = blockIdx.x*256 + threadIdx.x;
    unsigned bal = __ballot_sync(0xffffffffu, mask[gid] != 0);
    if ((gid & 31) == 0) g_maskbits[gid>>5] = bal;
}
__global__ void cvt_split(const float* __restrict__ src, unsigned* __restrict__ dh,
                          unsigned* __restrict__ dl, int n2){
    int i = blockIdx.x*256 + threadIdx.x;
    if (i < n2){
        float2 v = ((const float2*)src)[i];
        unsigned h, l; split2(v.x, v.y, h, l);
        dh[i] = h; dl[i] = l;
    }
}
__global__ void cvt_half(const float* __restrict__ src, unsigned* __restrict__ d, int n2){
    int i = blockIdx.x*256 + threadIdx.x;
    if (i < n2){
        float2 v = ((const float2*)src)[i];
        d[i] = packh(v.x, v.y);
    }
}

// ---------------------------------------------------------------------------
// QKV GEMM: [4096,768] @ [2304,768]^T, split-bf16 (3 mma), cp.async 2-stage.
// Epilogue: q (scaled) / k as fp16 hi+lo pairs, v as fp16 TRANSPOSED [d][s].
// ---------------------------------------------------------------------------
__global__ void __launch_bounds__(256) gemm_qkv()
{
    const int LDA = 20;
    extern __shared__ unsigned sm[];
    unsigned* SAh = sm;
    unsigned* SAl = sm + 2*2560;
    unsigned* SBh = sm + 4*2560;
    unsigned* SBl = sm + 6*2560;

    const int tid = threadIdx.x, lane = tid & 31, warp = tid >> 5;
    const int wm = warp >> 2, wn = warp & 3;
    const int m0 = blockIdx.y * 128, n0 = blockIdx.x * 128;

    float acc[4][4][4];
    #pragma unroll
    for (int i=0;i<4;i++) for (int j=0;j<4;j++) for (int e=0;e<4;e++) acc[i][j][e]=0.f;

    const int r = tid >> 2, ch = (tid & 3) * 4;
    auto issue = [&](int buf, int p0){
        unsigned* ah = SAh + buf*2560; unsigned* al = SAl + buf*2560;
        unsigned* bh = SBh + buf*2560; unsigned* bl = SBl + buf*2560;
        #pragma unroll
        for (int rep = 0; rep < 2; rep++){
            int rr = r + rep*64;
            cp16(&ah[rr*LDA + ch], g_xh  + (size_t)(m0+rr)*384 + p0 + ch);
            cp16(&al[rr*LDA + ch], g_xl  + (size_t)(m0+rr)*384 + p0 + ch);
            cp16(&bh[rr*LDA + ch], g_wqh + (size_t)(n0+rr)*384 + p0 + ch);
            cp16(&bl[rr*LDA + ch], g_wql + (size_t)(n0+rr)*384 + p0 + ch);
        }
    };

    const int T = 24;
    issue(0, 0); CP_COMMIT();
    for (int t = 0; t < T; t++){
        int buf = t & 1;
        if (t+1 < T){ issue(buf^1, (t+1)*16); CP_COMMIT(); CP_WAIT(1); }
        else CP_WAIT(0);
        __syncthreads();
        unsigned* ah_ = SAh + buf*2560; unsigned* al_ = SAl + buf*2560;
        unsigned* bh_ = SBh + buf*2560; unsigned* bl_ = SBl + buf*2560;
        #pragma unroll
        for (int ks = 0; ks < 2; ks++){
            const int q2 = ks*8 + (lane & 3);
            unsigned Ah[4][4], Al[4][4];
            #pragma unroll
            for (int mt=0; mt<4; mt++){
                int base = (wm*64 + mt*16 + (lane>>2))*LDA + q2;
                Ah[mt][0]=ah_[base];      Ah[mt][1]=ah_[base+8*LDA];
                Ah[mt][2]=ah_[base+4];    Ah[mt][3]=ah_[base+8*LDA+4];
                Al[mt][0]=al_[base];      Al[mt][1]=al_[base+8*LDA];
                Al[mt][2]=al_[base+4];    Al[mt][3]=al_[base+8*LDA+4];
            }
            #pragma unroll
            for (int nt=0; nt<4; nt++){
                int bbase = (wn*32 + nt*8 + (lane>>2))*LDA + q2;
                unsigned Bh[2] = { bh_[bbase], bh_[bbase+4] };
                unsigned Bl[2] = { bl_[bbase], bl_[bbase+4] };
                #pragma unroll
                for (int mt=0; mt<4; mt++){
                    mmabf(acc[mt][nt], Ah[mt], Bh);
                    mmabf(acc[mt][nt], Al[mt], Bh);
                    mmabf(acc[mt][nt], Ah[mt], Bl);
                }
            }
        }
        __syncthreads();
    }

    __half* vth = (__half*)g_vt;
    #pragma unroll
    for (int mt=0; mt<4; mt++){
        #pragma unroll
        for (int nt=0; nt<4; nt++){
            int m = m0 + wm*64 + mt*16 + (lane>>2);
            int n = n0 + wn*32 + nt*8 + 2*(lane&3);
            int which = (n >= 2*EMB) ? 2 : ((n >= EMB) ? 1 : 0);
            int rem = n - which*EMB;
            int hh = rem >> 6, dd = rem & 63;
            #pragma unroll
            for (int half_=0; half_<2; half_++){
                int mm = m + half_*8;
                float v0 = acc[mt][nt][half_*2], v1 = acc[mt][nt][half_*2+1];
                size_t base = (((size_t)(mm>>11)*NH + hh)*SEQ + (mm & (SEQ-1)));
                if (which == 0){
                    unsigned h,l; split2h(v0*0.125f, v1*0.125f, h, l);
                    g_qh[base*32 + (dd>>1)] = h; g_ql[base*32 + (dd>>1)] = l;
                } else if (which == 1){
                    unsigned h,l; split2h(v0, v1, h, l);
                    g_kh[base*32 + (dd>>1)] = h; g_kl[base*32 + (dd>>1)] = l;
                } else {
                    // transposed: [b,h][d][s]
                    size_t hb = ((size_t)(mm>>11)*NH + hh)*HD;
                    int sss = mm & (SEQ-1);
                    vth[(hb + dd)  *SEQ + sss] = __float2half_rn(v0);
                    vth[(hb + dd+1)*SEQ + sss] = __float2half_rn(v1);
                }
            }
        }
    }
}

// ---------------------------------------------------------------------------
// Flash attention: BQ=BKV=128. QK^T 2-term fp16 split, PV single fp16 with
// direct accumulator->A-fragment packing (no shuffles). V^T fp16 in smem.
// ---------------------------------------------------------------------------
__global__ void __launch_bounds__(256) flash_mma()
{
    const int LQ = 36;    // uints/row for Q,K (32 data + 4 pad)
    const int LVT = 68;   // uints/row for V^T (64 data + 4 pad)
    extern __shared__ unsigned smu[];
    unsigned* Qh = smu;                    // [128*36]
    unsigned* Ql = smu + 4608;
    unsigned* KH = smu + 9216;             // [2][128*36]
    unsigned* KL = smu + 18432;
    unsigned* VS = smu + 27648;            // [2][64*68]

    const int tid = threadIdx.x, lane = tid & 31, warp = tid >> 5;
    const int wq = warp * 16;
    const int q0 = blockIdx.x * 128;
    const int h = blockIdx.y, b = blockIdx.z;

    const size_t head = ((size_t)(b*NH + h)) * SEQ;
    const unsigned* qh = g_qh + head*32; const unsigned* ql = g_ql + head*32;
    const unsigned* kh = g_kh + head*32; const unsigned* kl = g_kl + head*32;
    const unsigned* vtu = g_vt + ((size_t)(b*NH + h)) * HD * (SEQ/2);

    for (int t = tid; t < 1024; t += 256){
        int r = t >> 3, c = (t & 7) * 4;
        cp16(&Qh[r*LQ + c], qh + (size_t)(q0 + r)*32 + c);
        cp16(&Ql[r*LQ + c], ql + (size_t)(q0 + r)*32 + c);
    }
    auto issue_kv = [&](int buf, int kt){
        unsigned* kh_ = KH + buf*4608; unsigned* kl_ = KL + buf*4608;
        unsigned* vs_ = VS + buf*4352;
        for (int t = tid; t < 1024; t += 256){
            int r = t >> 3, c = (t & 7) * 4;
            cp16(&kh_[r*LQ + c], kh + (size_t)(kt + r)*32 + c);
            cp16(&kl_[r*LQ + c], kl + (size_t)(kt + r)*32 + c);
        }
        for (int t = tid; t < 1024; t += 256){
            int d = t >> 4, c = (t & 15) * 4;
            cp16(&vs_[d*LVT + c], vtu + (size_t)d*(SEQ/2) + (kt>>1) + c);
        }
    };

    float mrow[2] = {-CUDART_INF_F, -CUDART_INF_F};
    float lsum[2] = {0.f, 0.f};
    float o[8][4];
    #pragma unroll
    for (int i=0;i<8;i++){ o[i][0]=o[i][1]=o[i][2]=o[i][3]=0.f; }

    const int rl0 = wq + (lane>>2);
    const unsigned* mrow0 = g_maskbits + (size_t)(q0 + rl0)     * (SEQ/32);
    const unsigned* mrow1 = g_maskbits + (size_t)(q0 + rl0 + 8) * (SEQ/32);

    issue_kv(0, 0); CP_COMMIT();
    const int T = SEQ/128;
    for (int t = 0; t < T; t++){
        int buf = t & 1;
        if (t+1 < T){ issue_kv(buf^1, (t+1)*128); CP_COMMIT(); CP_WAIT(1); }
        else CP_WAIT(0);
        __syncthreads();
        unsigned* kh_ = KH + buf*4608; unsigned* kl_ = KL + buf*4608;
        unsigned* vs_ = VS + buf*4352;
        const int kt = t*128;

        // S = Q K^T  (fp16 2-term: hi*hi + lo*hi)
        float s[16][4];
        #pragma unroll
        for (int nt=0; nt<16; nt++){ s[nt][0]=s[nt][1]=s[nt][2]=s[nt][3]=0.f; }

        #pragma unroll
        for (int ks = 0; ks < 4; ks++){
            const int q2 = ks*8 + (lane & 3);
            int abase = (wq + (lane>>2))*LQ + q2;
            unsigned Ah[4] = { Qh[abase], Qh[abase+8*LQ], Qh[abase+4], Qh[abase+8*LQ+4] };
            unsigned Al[4] = { Ql[abase], Ql[abase+8*LQ], Ql[abase+4], Ql[abase+8*LQ+4] };
            #pragma unroll
            for (int nt=0; nt<16; nt++){
                int bbase = (nt*8 + (lane>>2))*LQ + q2;
                unsigned Bh[2] = { kh_[bbase], kh_[bbase+4] };
                unsigned Bl[2] = { kl_[bbase], kl_[bbase+4] };
                mmah(s[nt], Ah, Bh);
                mmah(s[nt], Al, Bh);
            }
        }
        // + q_hi * k_lo term folded: (dropped by design; see 2-term analysis)

        // mask
        {
            int w = kt >> 5;
            unsigned w0[4] = { mrow0[w], mrow0[w+1], mrow0[w+2], mrow0[w+3] };
            unsigned w1[4] = { mrow1[w], mrow1[w+1], mrow1[w+2], mrow1[w+3] };
            if ((w0[0]&w0[1]&w0[2]&w0[3]&w1[0]&w1[1]&w1[2]&w1[3]) != 0xffffffffu){
                #pragma unroll
                for (int nt=0; nt<16; nt++){
                    #pragma unroll
                    for (int e=0; e<2; e++){
                        int c = nt*8 + 2*(lane&3) + e;
                        if (!((w0[c>>5] >> (c&31)) & 1u)) s[nt][e]   = -CUDART_INF_F;
                        if (!((w1[c>>5] >> (c&31)) & 1u)) s[nt][2+e] = -CUDART_INF_F;
                    }
                }
            }
        }

        // online softmax (rows rl0, rl0+8)
        float mx0 = -CUDART_INF_F, mx1 = -CUDART_INF_F;
        #pragma unroll
        for (int nt=0; nt<16; nt++){
            mx0 = fmaxf(mx0, fmaxf(s[nt][0], s[nt][1]));
            mx1 = fmaxf(mx1, fmaxf(s[nt][2], s[nt][3]));
        }
        mx0 = fmaxf(mx0, __shfl_xor_sync(0xffffffffu, mx0, 1));
        mx0 = fmaxf(mx0, __shfl_xor_sync(0xffffffffu, mx0, 2));
        mx1 = fmaxf(mx1, __shfl_xor_sync(0xffffffffu, mx1, 1));
        mx1 = fmaxf(mx1, __shfl_xor_sync(0xffffffffu, mx1, 2));
        float mn0 = fmaxf(mrow[0], mx0), mn1 = fmaxf(mrow[1], mx1);
        float corr0 = __expf(mrow[0]-mn0), corr1 = __expf(mrow[1]-mn1);
        mrow[0] = mn0; mrow[1] = mn1;
        float ps0 = 0.f, ps1 = 0.f;
        #pragma unroll
        for (int nt=0; nt<16; nt++){
            s[nt][0] = __expf(s[nt][0]-mn0); ps0 += s[nt][0];
            s[nt][1] = __expf(s[nt][1]-mn0); ps0 += s[nt][1];
            s[nt][2] = __expf(s[nt][2]-mn1); ps1 += s[nt][2];
            s[nt][3] = __expf(s[nt][3]-mn1); ps1 += s[nt][3];
        }
        ps0 += __shfl_xor_sync(0xffffffffu, ps0, 1);
        ps0 += __shfl_xor_sync(0xffffffffu, ps0, 2);
        ps1 += __shfl_xor_sync(0xffffffffu, ps1, 1);
        ps1 += __shfl_xor_sync(0xffffffffu, ps1, 2);
        lsum[0] = lsum[0]*corr0 + ps0;
        lsum[1] = lsum[1]*corr1 + ps1;
        #pragma unroll
        for (int i=0;i<8;i++){
            o[i][0]*=corr0; o[i][1]*=corr0; o[i][2]*=corr1; o[i][3]*=corr1;
        }

        // O += P V: accumulator fragments ARE fp16 A-fragments after packing
        #pragma unroll
        for (int st=0; st<8; st++){
            unsigned a[4];
            a[0] = packh(s[2*st][0],   s[2*st][1]);
            a[1] = packh(s[2*st][2],   s[2*st][3]);
            a[2] = packh(s[2*st+1][0], s[2*st+1][1]);
            a[3] = packh(s[2*st+1][2], s[2*st+1][3]);
            #pragma unroll
            for (int nd=0; nd<8; nd++){
                int bbase = (nd*8 + (lane>>2))*LVT + st*8 + (lane&3);
                unsigned bv[2] = { vs_[bbase], vs_[bbase + 4] };
                mmah(o[nd], a, bv);
            }
        }
        __syncthreads();
    }

    // epilogue: normalize + write ctx as packed fp16 pairs
    float inv0 = 1.0f/lsum[0], inv1 = 1.0f/lsum[1];
    int rg = q0 + wq + (lane>>2);
    #pragma unroll
    for (int nd=0; nd<8; nd++){
        int cu = h*32 + nd*4 + (lane&3);   // uint column (pair of fp16)
        g_ctxt[(size_t)(b*SEQ + rg)*384 + cu]     = packh(o[nd][0]*inv0, o[nd][1]*inv0);
        g_ctxt[(size_t)(b*SEQ + rg + 8)*384 + cu] = packh(o[nd][2]*inv1, o[nd][3]*inv1);
    }
}

// ---------------------------------------------------------------------------
// Out projection: [4096,768] @ [768,768]^T + bias, single fp16 k16, cp.async.
// ---------------------------------------------------------------------------
__global__ void __launch_bounds__(256) gemm_out(const float* __restrict__ bias,
                                                float* __restrict__ C)
{
    const int LDA = 20;
    extern __shared__ unsigned sm[];
    unsigned* SA = sm;              // [2][128*20]
    unsigned* SB = sm + 2*2560;

    const int tid = threadIdx.x, lane = tid & 31, warp = tid >> 5;
    const int wm = warp >> 2, wn = warp & 3;
    const int m0 = blockIdx.y * 128, n0 = blockIdx.x * 128;

    float acc[4][4][4];
    #pragma unroll
    for (int i=0;i<4;i++) for (int j=0;j<4;j++) for (int e=0;e<4;e++) acc[i][j][e]=0.f;

    const int r = tid >> 1, ch = (tid & 1) * 8;
    auto issue = [&](int buf, int p0){
        unsigned* a_ = SA + buf*2560; unsigned* b_ = SB + buf*2560;
        cp16(&a_[r*LDA + ch],     g_ctxt + (size_t)(m0+r)*384 + p0 + ch);
        cp16(&a_[r*LDA + ch + 4], g_ctxt + (size_t)(m0+r)*384 + p0 + ch + 4);
        cp16(&b_[r*LDA + ch],     g_wot  + (size_t)(n0+r)*384 + p0 + ch);
        cp16(&b_[r*LDA + ch + 4], g_wot  + (size_t)(n0+r)*384 + p0 + ch + 4);
    };

    const int T = 24;   // 768 / 32 k per tile (16 uints)
    issue(0, 0); CP_COMMIT();
    for (int t = 0; t < T; t++){
        int buf = t & 1;
        if (t+1 < T){ issue(buf^1, (t+1)*16); CP_COMMIT(); CP_WAIT(1); }
        else CP_WAIT(0);
        __syncthreads();
        unsigned* a_ = SA + buf*2560; unsigned* b_ = SB + buf*2560;
        #pragma unroll
        for (int ks = 0; ks < 2; ks++){
            const int q2 = ks*8 + (lane & 3);
            unsigned A[4][4];
            #pragma unroll
            for (int mt=0; mt<4; mt++){
                int base = (wm*64 + mt*16 + (lane>>2))*LDA + q2;
                A[mt][0]=a_[base];   A[mt][1]=a_[base+8*LDA];
                A[mt][2]=a_[base+4]; A[mt][3]=a_[base+8*LDA+4];
            }
            #pragma unroll
            for (int nt=0; nt<4; nt++){
                int bbase = (wn*32 + nt*8 + (lane>>2))*LDA + q2;
                unsigned B[2] = { b_[bbase], b_[bbase+4] };
                #pragma unroll
                for (int mt=0; mt<4; mt++) mmah(acc[mt][nt], A[mt], B);
            }
        }
        __syncthreads();
    }

    #pragma unroll
    for (int mt=0; mt<4; mt++){
        #pragma unroll
        for (int nt=0; nt<4; nt++){
            int m = m0 + wm*64 + mt*16 + (lane>>2);
            int n = n0 + wn*32 + nt*8 + 2*(lane&3);
            float2 bv = *(const float2*)&bias[n];
            float2 v0 = make_float2(acc[mt][nt][0]+bv.x, acc[mt][nt][1]+bv.y);
            float2 v1 = make_float2(acc[mt][nt][2]+bv.x, acc[mt][nt][3]+bv.y);
            *(float2*)&C[(size_t)m*EMB + n] = v0;
            *(float2*)&C[(size_t)(m+8)*EMB + n] = v1;
        }
    }
}

// ---------------------------------------------------------------------------
extern "C" void kernel_launch(void* const* d_in, const int* in_sizes, int n_in,
                              void* d_out, int out_size)
{
    const float* x     = (const float*)d_in[0];
    const int*   mask  = (const int*)  d_in[1];
    const float* w_qkv = (const float*)d_in[2];
    const float* w_out = (const float*)d_in[3];
    const float* b_out = (const float*)d_in[4];
    float* out = (float*)d_out;

    static unsigned *p_xh=nullptr,*p_xl,*p_wqh,*p_wql,*p_wot;
    if (!p_xh){
        cudaGetSymbolAddress((void**)&p_xh,  g_xh);
        cudaGetSymbolAddress((void**)&p_xl,  g_xl);
        cudaGetSymbolAddress((void**)&p_wqh, g_wqh);
        cudaGetSymbolAddress((void**)&p_wql, g_wql);
        cudaGetSymbolAddress((void**)&p_wot, g_wot);
    }

    pack_mask<<<SEQ*SEQ/32/8, 256>>>(mask);
    cvt_split<<<(MROWS*384)/256, 256>>>(x,     p_xh,  p_xl,  MROWS*384);
    cvt_split<<<(2304*384)/256, 256>>>(w_qkv, p_wqh, p_wql, 2304*384);
    cvt_half <<<(EMB*EMB/2)/256, 256>>>(w_out, p_wot, EMB*EMB/2);

    {   // QKV projection
        cudaFuncSetAttribute(gemm_qkv, cudaFuncAttributeMaxDynamicSharedMemorySize, 81920);
        dim3 grid(2304/128, MROWS/128);   // 18 x 32
        gemm_qkv<<<grid, 256, 81920>>>();
    }
    {   // flash attention
        const int smem_bytes = (27648 + 2*4352) * 4;   // 145408
        cudaFuncSetAttribute(flash_mma, cudaFuncAttributeMaxDynamicSharedMemorySize, smem_bytes);
        dim3 grid(SEQ/128, NH, NB);       // 16 x 12 x 2
        flash_mma<<<grid, 256, smem_bytes>>>();
    }
    {   // out projection
        dim3 grid(EMB/128, MROWS/128);    // 6 x 32
        gemm_out<<<grid, 256, 40960>>>(b_out, out);
    }
}

// round 5
// speedup vs baseline: 4.7293x; 1.0175x over previous
#include <cuda_runtime.h>
#include <cuda_bf16.h>
#include <cuda_fp16.h>
#include <math_constants.h>

#define NH 12
#define HD 64
#define EMB 768
#define NB 2
#define SEQ 2048
#define MROWS (NB*SEQ)   // 4096

// ---------------- device-global scratch (no allocation allowed) -------------
__device__ unsigned g_xh[(size_t)MROWS*384],  g_xl[(size_t)MROWS*384];   // bf16 split pairs
__device__ unsigned g_wqh[(size_t)2304*384],  g_wql[(size_t)2304*384];
__device__ unsigned g_wot[(size_t)EMB*EMB/2];                            // fp16 pairs
__device__ unsigned g_qh[(size_t)NB*NH*SEQ*32], g_ql[(size_t)NB*NH*SEQ*32]; // fp16 split pairs
__device__ unsigned g_kh[(size_t)NB*NH*SEQ*32], g_kl[(size_t)NB*NH*SEQ*32];
__device__ unsigned g_vt[(size_t)NB*NH*HD*SEQ/2];                        // V^T fp16 [b,h][d][s]
__device__ unsigned g_ctxt[(size_t)MROWS*384];                           // ctx fp16 pairs
__device__ unsigned g_maskbits[(size_t)SEQ*SEQ/32];

// ---------------- helpers ----------------------------------------------------
__device__ __forceinline__ void split2(float x0, float x1, unsigned &hi, unsigned &lo){
    __nv_bfloat162 h = __floats2bfloat162_rn(x0, x1);
    float r0 = x0 - __low2float(h);
    float r1 = x1 - __high2float(h);
    __nv_bfloat162 l = __floats2bfloat162_rn(r0, r1);
    hi = *reinterpret_cast<unsigned*>(&h);
    lo = *reinterpret_cast<unsigned*>(&l);
}
__device__ __forceinline__ void split2h(float x0, float x1, unsigned &hi, unsigned &lo){
    __half2 h = __floats2half2_rn(x0, x1);
    float r0 = x0 - __low2float(h);
    float r1 = x1 - __high2float(h);
    __half2 l = __floats2half2_rn(r0, r1);
    hi = *reinterpret_cast<unsigned*>(&h);
    lo = *reinterpret_cast<unsigned*>(&l);
}
__device__ __forceinline__ unsigned packh(float x0, float x1){
    __half2 h = __floats2half2_rn(x0, x1);
    return *reinterpret_cast<unsigned*>(&h);
}
__device__ __forceinline__ void mmabf(float c[4], const unsigned a[4], const unsigned b[2]){
    asm volatile("mma.sync.aligned.m16n8k16.row.col.f32.bf16.bf16.f32 "
        "{%0,%1,%2,%3},{%4,%5,%6,%7},{%8,%9},{%0,%1,%2,%3};"
        : "+f"(c[0]), "+f"(c[1]), "+f"(c[2]), "+f"(c[3])
        : "r"(a[0]), "r"(a[1]), "r"(a[2]), "r"(a[3]), "r"(b[0]), "r"(b[1]));
}
__device__ __forceinline__ void mmah(float c[4], const unsigned a[4], const unsigned b[2]){
    asm volatile("mma.sync.aligned.m16n8k16.row.col.f32.f16.f16.f32 "
        "{%0,%1,%2,%3},{%4,%5,%6,%7},{%8,%9},{%0,%1,%2,%3};"
        : "+f"(c[0]), "+f"(c[1]), "+f"(c[2]), "+f"(c[3])
        : "r"(a[0]), "r"(a[1]), "r"(a[2]), "r"(a[3]), "r"(b[0]), "r"(b[1]));
}
__device__ __forceinline__ void cp16(void* s, const void* g){
    unsigned sa = (unsigned)__cvta_generic_to_shared(s);
    asm volatile("cp.async.cg.shared.global [%0], [%1], 16;" :: "r"(sa), "l"(g));
}
#define CP_COMMIT() asm volatile("cp.async.commit_group;")
#define CP_WAIT(n)  asm volatile("cp.async.wait_group %0;" :: "n"(n))

// ---------------- small prep kernels -----------------------------------------
__global__ void pack_mask(const int* __restrict__ mask){
    int gid = blockIdx.x*256 + threadIdx.x;
    unsigned bal = __ballot_sync(0xffffffffu, mask[gid] != 0);
    if ((gid & 31) == 0) g_maskbits[gid>>5] = bal;
}
__global__ void cvt_split(const float* __restrict__ src, unsigned* __restrict__ dh,
                          unsigned* __restrict__ dl, int n2){
    int i = blockIdx.x*256 + threadIdx.x;
    if (i < n2){
        float2 v = ((const float2*)src)[i];
        unsigned h, l; split2(v.x, v.y, h, l);
        dh[i] = h; dl[i] = l;
    }
}
__global__ void cvt_half(const float* __restrict__ src, unsigned* __restrict__ d, int n2){
    int i = blockIdx.x*256 + threadIdx.x;
    if (i < n2){
        float2 v = ((const float2*)src)[i];
        d[i] = packh(v.x, v.y);
    }
}

// ---------------------------------------------------------------------------
// QKV GEMM: [4096,768] @ [2304,768]^T, split-bf16 (3 mma), cp.async 2-stage.
// Epilogue: q (scaled) / k as fp16 hi+lo pairs, v as fp16 TRANSPOSED [d][s].
// ---------------------------------------------------------------------------
__global__ void __launch_bounds__(256) gemm_qkv()
{
    const int LDA = 20;
    extern __shared__ unsigned sm[];
    unsigned* SAh = sm;
    unsigned* SAl = sm + 2*2560;
    unsigned* SBh = sm + 4*2560;
    unsigned* SBl = sm + 6*2560;

    const int tid = threadIdx.x, lane = tid & 31, warp = tid >> 5;
    const int wm = warp >> 2, wn = warp & 3;
    const int m0 = blockIdx.y * 128, n0 = blockIdx.x * 128;

    float acc[4][4][4];
    #pragma unroll
    for (int i=0;i<4;i++) for (int j=0;j<4;j++) for (int e=0;e<4;e++) acc[i][j][e]=0.f;

    const int r = tid >> 2, ch = (tid & 3) * 4;
    auto issue = [&](int buf, int p0){
        unsigned* ah = SAh + buf*2560; unsigned* al = SAl + buf*2560;
        unsigned* bh = SBh + buf*2560; unsigned* bl = SBl + buf*2560;
        #pragma unroll
        for (int rep = 0; rep < 2; rep++){
            int rr = r + rep*64;
            cp16(&ah[rr*LDA + ch], g_xh  + (size_t)(m0+rr)*384 + p0 + ch);
            cp16(&al[rr*LDA + ch], g_xl  + (size_t)(m0+rr)*384 + p0 + ch);
            cp16(&bh[rr*LDA + ch], g_wqh + (size_t)(n0+rr)*384 + p0 + ch);
            cp16(&bl[rr*LDA + ch], g_wql + (size_t)(n0+rr)*384 + p0 + ch);
        }
    };

    const int T = 24;
    issue(0, 0); CP_COMMIT();
    for (int t = 0; t < T; t++){
        int buf = t & 1;
        if (t+1 < T){ issue(buf^1, (t+1)*16); CP_COMMIT(); CP_WAIT(1); }
        else CP_WAIT(0);
        __syncthreads();
        unsigned* ah_ = SAh + buf*2560; unsigned* al_ = SAl + buf*2560;
        unsigned* bh_ = SBh + buf*2560; unsigned* bl_ = SBl + buf*2560;
        #pragma unroll
        for (int ks = 0; ks < 2; ks++){
            const int q2 = ks*8 + (lane & 3);
            unsigned Ah[4][4], Al[4][4];
            #pragma unroll
            for (int mt=0; mt<4; mt++){
                int base = (wm*64 + mt*16 + (lane>>2))*LDA + q2;
                Ah[mt][0]=ah_[base];      Ah[mt][1]=ah_[base+8*LDA];
                Ah[mt][2]=ah_[base+4];    Ah[mt][3]=ah_[base+8*LDA+4];
                Al[mt][0]=al_[base];      Al[mt][1]=al_[base+8*LDA];
                Al[mt][2]=al_[base+4];    Al[mt][3]=al_[base+8*LDA+4];
            }
            #pragma unroll
            for (int nt=0; nt<4; nt++){
                int bbase = (wn*32 + nt*8 + (lane>>2))*LDA + q2;
                unsigned Bh[2] = { bh_[bbase], bh_[bbase+4] };
                unsigned Bl[2] = { bl_[bbase], bl_[bbase+4] };
                #pragma unroll
                for (int mt=0; mt<4; mt++){
                    mmabf(acc[mt][nt], Ah[mt], Bh);
                    mmabf(acc[mt][nt], Al[mt], Bh);
                    mmabf(acc[mt][nt], Ah[mt], Bl);
                }
            }
        }
        __syncthreads();
    }

    __half* vth = (__half*)g_vt;
    #pragma unroll
    for (int mt=0; mt<4; mt++){
        #pragma unroll
        for (int nt=0; nt<4; nt++){
            int m = m0 + wm*64 + mt*16 + (lane>>2);
            int n = n0 + wn*32 + nt*8 + 2*(lane&3);
            int which = (n >= 2*EMB) ? 2 : ((n >= EMB) ? 1 : 0);
            int rem = n - which*EMB;
            int hh = rem >> 6, dd = rem & 63;
            #pragma unroll
            for (int half_=0; half_<2; half_++){
                int mm = m + half_*8;
                float v0 = acc[mt][nt][half_*2], v1 = acc[mt][nt][half_*2+1];
                size_t base = (((size_t)(mm>>11)*NH + hh)*SEQ + (mm & (SEQ-1)));
                if (which == 0){
                    unsigned h,l; split2h(v0*0.125f, v1*0.125f, h, l);
                    g_qh[base*32 + (dd>>1)] = h; g_ql[base*32 + (dd>>1)] = l;
                } else if (which == 1){
                    unsigned h,l; split2h(v0, v1, h, l);
                    g_kh[base*32 + (dd>>1)] = h; g_kl[base*32 + (dd>>1)] = l;
                } else {
                    size_t hb = ((size_t)(mm>>11)*NH + hh)*HD;
                    int sss = mm & (SEQ-1);
                    vth[(hb + dd)  *SEQ + sss] = __float2half_rn(v0);
                    vth[(hb + dd+1)*SEQ + sss] = __float2half_rn(v1);
                }
            }
        }
    }
}

// ---------------------------------------------------------------------------
// Flash attention v2: BQ=128, BKV=64. Q fragments in REGISTERS (no smem).
// QK^T 2-term fp16 split; PV fp16 direct accumulator packing, V^T in smem.
// 54KB smem + <=128 regs -> 2 CTAs/SM.
// ---------------------------------------------------------------------------
__global__ void __launch_bounds__(256, 2) flash_mma()
{
    const int LK = 36;    // uints/row (32 data + 4 pad)
    extern __shared__ unsigned smu[];
    unsigned* KH = smu;               // [2][64*36]
    unsigned* KL = smu + 2*2304;
    unsigned* VS = smu + 4*2304;      // [2][64*36]  V^T (d rows, 32 s-pair uints)

    const int tid = threadIdx.x, lane = tid & 31, warp = tid >> 5;
    const int wq = warp * 16;
    const int q0 = blockIdx.x * 128;
    const int h = blockIdx.y, b = blockIdx.z;

    const size_t head = ((size_t)(b*NH + h)) * SEQ;
    const unsigned* qh = g_qh + head*32; const unsigned* ql = g_ql + head*32;
    const unsigned* kh = g_kh + head*32; const unsigned* kl = g_kl + head*32;
    const unsigned* vtu = g_vt + ((size_t)(b*NH + h)) * HD * (SEQ/2);

    // Q fragments -> registers (once per CTA)
    unsigned Aq[4][4], Aql[4][4];
    {
        const size_t r0 = q0 + wq + (lane>>2);
        #pragma unroll
        for (int ks = 0; ks < 4; ks++){
            const int q2 = ks*8 + (lane & 3);
            Aq[ks][0]  = qh[r0*32 + q2];       Aq[ks][1]  = qh[(r0+8)*32 + q2];
            Aq[ks][2]  = qh[r0*32 + q2 + 4];   Aq[ks][3]  = qh[(r0+8)*32 + q2 + 4];
            Aql[ks][0] = ql[r0*32 + q2];       Aql[ks][1] = ql[(r0+8)*32 + q2];
            Aql[ks][2] = ql[r0*32 + q2 + 4];   Aql[ks][3] = ql[(r0+8)*32 + q2 + 4];
        }
    }

    auto issue_kv = [&](int buf, int kt){
        unsigned* kh_ = KH + buf*2304; unsigned* kl_ = KL + buf*2304;
        unsigned* vs_ = VS + buf*2304;
        #pragma unroll
        for (int t2 = tid; t2 < 512; t2 += 256){
            int r = t2 >> 3, c = (t2 & 7) * 4;
            cp16(&kh_[r*LK + c], kh + (size_t)(kt + r)*32 + c);
            cp16(&kl_[r*LK + c], kl + (size_t)(kt + r)*32 + c);
            cp16(&vs_[r*LK + c], vtu + (size_t)r*(SEQ/2) + (kt>>1) + c);
        }
    };

    float mrow[2] = {-CUDART_INF_F, -CUDART_INF_F};
    float lsum[2] = {0.f, 0.f};
    float o[8][4];
    #pragma unroll
    for (int i=0;i<8;i++){ o[i][0]=o[i][1]=o[i][2]=o[i][3]=0.f; }

    const int rl0 = wq + (lane>>2);
    const unsigned* mrow0 = g_maskbits + (size_t)(q0 + rl0)     * (SEQ/32);
    const unsigned* mrow1 = g_maskbits + (size_t)(q0 + rl0 + 8) * (SEQ/32);

    issue_kv(0, 0); CP_COMMIT();
    const int T = SEQ/64;   // 32
    for (int t = 0; t < T; t++){
        int buf = t & 1;
        if (t+1 < T){ issue_kv(buf^1, (t+1)*64); CP_COMMIT(); CP_WAIT(1); }
        else CP_WAIT(0);
        __syncthreads();
        unsigned* kh_ = KH + buf*2304; unsigned* kl_ = KL + buf*2304;
        unsigned* vs_ = VS + buf*2304;
        const int kt = t*64;

        // S = Q K^T  (fp16 2-term: q_hi*k + q_lo*k_hi)
        float s[8][4];
        #pragma unroll
        for (int nt=0; nt<8; nt++){ s[nt][0]=s[nt][1]=s[nt][2]=s[nt][3]=0.f; }

        #pragma unroll
        for (int ks = 0; ks < 4; ks++){
            const int q2 = ks*8 + (lane & 3);
            #pragma unroll
            for (int nt=0; nt<8; nt++){
                int bbase = (nt*8 + (lane>>2))*LK + q2;
                unsigned Bh[2] = { kh_[bbase], kh_[bbase+4] };
                unsigned Bl[2] = { kl_[bbase], kl_[bbase+4] };
                mmah(s[nt], Aq[ks], Bh);
                mmah(s[nt], Aql[ks], Bh);
                mmah(s[nt], Aq[ks], Bl);
            }
        }

        // mask (2 words per row per 64-wide tile)
        {
            int w = kt >> 5;
            unsigned w0[2] = { mrow0[w], mrow0[w+1] };
            unsigned w1[2] = { mrow1[w], mrow1[w+1] };
            if ((w0[0]&w0[1]&w1[0]&w1[1]) != 0xffffffffu){
                #pragma unroll
                for (int nt=0; nt<8; nt++){
                    #pragma unroll
                    for (int e=0; e<2; e++){
                        int c = nt*8 + 2*(lane&3) + e;
                        if (!((w0[c>>5] >> (c&31)) & 1u)) s[nt][e]   = -CUDART_INF_F;
                        if (!((w1[c>>5] >> (c&31)) & 1u)) s[nt][2+e] = -CUDART_INF_F;
                    }
                }
            }
        }

        // online softmax (rows rl0, rl0+8)
        float mx0 = -CUDART_INF_F, mx1 = -CUDART_INF_F;
        #pragma unroll
        for (int nt=0; nt<8; nt++){
            mx0 = fmaxf(mx0, fmaxf(s[nt][0], s[nt][1]));
            mx1 = fmaxf(mx1, fmaxf(s[nt][2], s[nt][3]));
        }
        mx0 = fmaxf(mx0, __shfl_xor_sync(0xffffffffu, mx0, 1));
        mx0 = fmaxf(mx0, __shfl_xor_sync(0xffffffffu, mx0, 2));
        mx1 = fmaxf(mx1, __shfl_xor_sync(0xffffffffu, mx1, 1));
        mx1 = fmaxf(mx1, __shfl_xor_sync(0xffffffffu, mx1, 2));
        float mn0 = fmaxf(mrow[0], mx0), mn1 = fmaxf(mrow[1], mx1);
        float corr0 = __expf(mrow[0]-mn0), corr1 = __expf(mrow[1]-mn1);
        mrow[0] = mn0; mrow[1] = mn1;
        float ps0 = 0.f, ps1 = 0.f;
        #pragma unroll
        for (int nt=0; nt<8; nt++){
            s[nt][0] = __expf(s[nt][0]-mn0); ps0 += s[nt][0];
            s[nt][1] = __expf(s[nt][1]-mn0); ps0 += s[nt][1];
            s[nt][2] = __expf(s[nt][2]-mn1); ps1 += s[nt][2];
            s[nt][3] = __expf(s[nt][3]-mn1); ps1 += s[nt][3];
        }
        ps0 += __shfl_xor_sync(0xffffffffu, ps0, 1);
        ps0 += __shfl_xor_sync(0xffffffffu, ps0, 2);
        ps1 += __shfl_xor_sync(0xffffffffu, ps1, 1);
        ps1 += __shfl_xor_sync(0xffffffffu, ps1, 2);
        lsum[0] = lsum[0]*corr0 + ps0;
        lsum[1] = lsum[1]*corr1 + ps1;
        #pragma unroll
        for (int i=0;i<8;i++){
            o[i][0]*=corr0; o[i][1]*=corr0; o[i][2]*=corr1; o[i][3]*=corr1;
        }

        // O += P V: accumulator fragments ARE fp16 A-fragments after packing
        #pragma unroll
        for (int st=0; st<4; st++){
            unsigned a[4];
            a[0] = packh(s[2*st][0],   s[2*st][1]);
            a[1] = packh(s[2*st][2],   s[2*st][3]);
            a[2] = packh(s[2*st+1][0], s[2*st+1][1]);
            a[3] = packh(s[2*st+1][2], s[2*st+1][3]);
            #pragma unroll
            for (int nd=0; nd<8; nd++){
                int bbase = (nd*8 + (lane>>2))*LK + st*8 + (lane&3);
                unsigned bv[2] = { vs_[bbase], vs_[bbase + 4] };
                mmah(o[nd], a, bv);
            }
        }
        __syncthreads();
    }

    // epilogue: normalize + write ctx as packed fp16 pairs
    float inv0 = 1.0f/lsum[0], inv1 = 1.0f/lsum[1];
    int rg = q0 + wq + (lane>>2);
    #pragma unroll
    for (int nd=0; nd<8; nd++){
        int cu = h*32 + nd*4 + (lane&3);
        g_ctxt[(size_t)(b*SEQ + rg)*384 + cu]     = packh(o[nd][0]*inv0, o[nd][1]*inv0);
        g_ctxt[(size_t)(b*SEQ + rg + 8)*384 + cu] = packh(o[nd][2]*inv1, o[nd][3]*inv1);
    }
}

// ---------------------------------------------------------------------------
// Out projection: [4096,768] @ [768,768]^T + bias, single fp16 k16, cp.async.
// ---------------------------------------------------------------------------
__global__ void __launch_bounds__(256) gemm_out(const float* __restrict__ bias,
                                                float* __restrict__ C)
{
    const int LDA = 20;
    extern __shared__ unsigned sm[];
    unsigned* SA = sm;
    unsigned* SB = sm + 2*2560;

    const int tid = threadIdx.x, lane = tid & 31, warp = tid >> 5;
    const int wm = warp >> 2, wn = warp & 3;
    const int m0 = blockIdx.y * 128, n0 = blockIdx.x * 128;

    float acc[4][4][4];
    #pragma unroll
    for (int i=0;i<4;i++) for (int j=0;j<4;j++) for (int e=0;e<4;e++) acc[i][j][e]=0.f;

    const int r = tid >> 1, ch = (tid & 1) * 8;
    auto issue = [&](int buf, int p0){
        unsigned* a_ = SA + buf*2560; unsigned* b_ = SB + buf*2560;
        cp16(&a_[r*LDA + ch],     g_ctxt + (size_t)(m0+r)*384 + p0 + ch);
        cp16(&a_[r*LDA + ch + 4], g_ctxt + (size_t)(m0+r)*384 + p0 + ch + 4);
        cp16(&b_[r*LDA + ch],     g_wot  + (size_t)(n0+r)*384 + p0 + ch);
        cp16(&b_[r*LDA + ch + 4], g_wot  + (size_t)(n0+r)*384 + p0 + ch + 4);
    };

    const int T = 24;
    issue(0, 0); CP_COMMIT();
    for (int t = 0; t < T; t++){
        int buf = t & 1;
        if (t+1 < T){ issue(buf^1, (t+1)*16); CP_COMMIT(); CP_WAIT(1); }
        else CP_WAIT(0);
        __syncthreads();
        unsigned* a_ = SA + buf*2560; unsigned* b_ = SB + buf*2560;
        #pragma unroll
        for (int ks = 0; ks < 2; ks++){
            const int q2 = ks*8 + (lane & 3);
            unsigned A[4][4];
            #pragma unroll
            for (int mt=0; mt<4; mt++){
                int base = (wm*64 + mt*16 + (lane>>2))*LDA + q2;
                A[mt][0]=a_[base];   A[mt][1]=a_[base+8*LDA];
                A[mt][2]=a_[base+4]; A[mt][3]=a_[base+8*LDA+4];
            }
            #pragma unroll
            for (int nt=0; nt<4; nt++){
                int bbase = (wn*32 + nt*8 + (lane>>2))*LDA + q2;
                unsigned B[2] = { b_[bbase], b_[bbase+4] };
                #pragma unroll
                for (int mt=0; mt<4; mt++) mmah(acc[mt][nt], A[mt], B);
            }
        }
        __syncthreads();
    }

    #pragma unroll
    for (int mt=0; mt<4; mt++){
        #pragma unroll
        for (int nt=0; nt<4; nt++){
            int m = m0 + wm*64 + mt*16 + (lane>>2);
            int n = n0 + wn*32 + nt*8 + 2*(lane&3);
            float2 bv = *(const float2*)&bias[n];
            float2 v0 = make_float2(acc[mt][nt][0]+bv.x, acc[mt][nt][1]+bv.y);
            float2 v1 = make_float2(acc[mt][nt][2]+bv.x, acc[mt][nt][3]+bv.y);
            *(float2*)&C[(size_t)m*EMB + n] = v0;
            *(float2*)&C[(size_t)(m+8)*EMB + n] = v1;
        }
    }
}

// ---------------------------------------------------------------------------
extern "C" void kernel_launch(void* const* d_in, const int* in_sizes, int n_in,
                              void* d_out, int out_size)
{
    const float* x     = (const float*)d_in[0];
    const int*   mask  = (const int*)  d_in[1];
    const float* w_qkv = (const float*)d_in[2];
    const float* w_out = (const float*)d_in[3];
    const float* b_out = (const float*)d_in[4];
    float* out = (float*)d_out;

    static unsigned *p_xh=nullptr,*p_xl,*p_wqh,*p_wql,*p_wot;
    if (!p_xh){
        cudaGetSymbolAddress((void**)&p_xh,  g_xh);
        cudaGetSymbolAddress((void**)&p_xl,  g_xl);
        cudaGetSymbolAddress((void**)&p_wqh, g_wqh);
        cudaGetSymbolAddress((void**)&p_wql, g_wql);
        cudaGetSymbolAddress((void**)&p_wot, g_wot);
    }

    pack_mask<<<SEQ*SEQ/32/8, 256>>>(mask);
    cvt_split<<<(MROWS*384)/256, 256>>>(x,     p_xh,  p_xl,  MROWS*384);
    cvt_split<<<(2304*384)/256, 256>>>(w_qkv, p_wqh, p_wql, 2304*384);
    cvt_half <<<(EMB*EMB/2)/256, 256>>>(w_out, p_wot, EMB*EMB/2);

    {   // QKV projection
        cudaFuncSetAttribute(gemm_qkv, cudaFuncAttributeMaxDynamicSharedMemorySize, 81920);
        dim3 grid(2304/128, MROWS/128);   // 18 x 32
        gemm_qkv<<<grid, 256, 81920>>>();
    }
    {   // flash attention (BKV=64, Q in regs, 2 CTAs/SM)
        const int smem_bytes = 6*2304*4;   // 55296
        cudaFuncSetAttribute(flash_mma, cudaFuncAttributeMaxDynamicSharedMemorySize, smem_bytes);
        dim3 grid(SEQ/128, NH, NB);        // 16 x 12 x 2
        flash_mma<<<grid, 256, smem_bytes>>>();
    }
    {   // out projection
        dim3 grid(EMB/128, MROWS/128);    // 6 x 32
        gemm_out<<<grid, 256, 40960>>>(b_out, out);
    }
}